// round 1
// baseline (speedup 1.0000x reference)
#include <cuda_runtime.h>
#include <math.h>

#define S_LEN 2048
#define EMB   1024
#define DH    64
#define NH    16

// Scratch (device globals: no allocations allowed)
__device__ float g_KQV[3 * S_LEN * DH];            // K,Q,V after shared projection
__device__ float g_H[3 * NH * S_LEN * DH];         // Kh,Qh,Vh per head
__device__ float g_cat[S_LEN * EMB];               // concatenated attention output
__device__ float g_y[S_LEN * EMB];                 // pre-LayerNorm (proj + bias + residual)

// ---------------------------------------------------------------------------
// Generic C = A @ B^T (+bias) (+res), A:[M,K] B:[N,K] row-major.
// 64x64 block, 256 threads, 4x4 microtile, KT=16.
// Smem stored transposed [k][m] with XOR swizzle (phys col = col ^ (k&12)) so
// compute reads are float4 and stores are ~2-way at worst.
// blockIdx.z selects a slice of B / bias / C (per-head batching).
// ---------------------------------------------------------------------------
__global__ __launch_bounds__(256) void gemm_abt(
    const float* __restrict__ A, const float* __restrict__ B,
    const float* __restrict__ bias, const float* __restrict__ res,
    float* __restrict__ C, int M, int N, int K,
    long long sBz, long long sBiasz, long long sCz)
{
    __shared__ float AsT[16 * 64];
    __shared__ float BsT[16 * 64];

    const int t  = threadIdx.x;
    const int tx = t & 15;
    const int ty = t >> 4;
    const int bm = blockIdx.x * 64;
    const int bn = blockIdx.y * 64;
    const int z  = blockIdx.z;

    B += (long long)z * sBz;
    C += (long long)z * sCz;
    const float* biasz = bias ? (bias + (long long)z * sBiasz) : nullptr;

    const int lm  = t >> 2;         // 0..63 (row within tile)
    const int kb4 = (t & 3) << 2;   // 0,4,8,12 (k sub-offset)

    float acc[4][4] = {};

    for (int kc = 0; kc < K; kc += 16) {
        float4 av = *(const float4*)(A + (long long)(bm + lm) * K + kc + kb4);
        float4 bv = *(const float4*)(B + (long long)(bn + lm) * K + kc + kb4);
        __syncthreads();
        AsT[(kb4 + 0) * 64 + (lm ^ ((kb4 + 0) & 12))] = av.x;
        AsT[(kb4 + 1) * 64 + (lm ^ ((kb4 + 1) & 12))] = av.y;
        AsT[(kb4 + 2) * 64 + (lm ^ ((kb4 + 2) & 12))] = av.z;
        AsT[(kb4 + 3) * 64 + (lm ^ ((kb4 + 3) & 12))] = av.w;
        BsT[(kb4 + 0) * 64 + (lm ^ ((kb4 + 0) & 12))] = bv.x;
        BsT[(kb4 + 1) * 64 + (lm ^ ((kb4 + 1) & 12))] = bv.y;
        BsT[(kb4 + 2) * 64 + (lm ^ ((kb4 + 2) & 12))] = bv.z;
        BsT[(kb4 + 3) * 64 + (lm ^ ((kb4 + 3) & 12))] = bv.w;
        __syncthreads();

#pragma unroll
        for (int kk = 0; kk < 16; kk++) {
            const int sw = kk & 12;
            float4 a = *(const float4*)&AsT[kk * 64 + ((4 * ty) ^ sw)];
            float4 b = *(const float4*)&BsT[kk * 64 + ((4 * tx) ^ sw)];
            float ar[4] = {a.x, a.y, a.z, a.w};
            float br[4] = {b.x, b.y, b.z, b.w};
#pragma unroll
            for (int i = 0; i < 4; i++)
#pragma unroll
                for (int j = 0; j < 4; j++)
                    acc[i][j] = fmaf(ar[i], br[j], acc[i][j]);
        }
    }

#pragma unroll
    for (int i = 0; i < 4; i++) {
        const int row = bm + 4 * ty + i;
        const int col = bn + 4 * tx;
        float4 c = make_float4(acc[i][0], acc[i][1], acc[i][2], acc[i][3]);
        if (biasz) {
            float4 bb = *(const float4*)&biasz[col];
            c.x += bb.x; c.y += bb.y; c.z += bb.z; c.w += bb.w;
        }
        if (res) {
            float4 rr = *(const float4*)&res[(long long)row * N + col];
            c.x += rr.x; c.y += rr.y; c.z += rr.z; c.w += rr.w;
        }
        *(float4*)&C[(long long)row * N + col] = c;
    }
}

// ---------------------------------------------------------------------------
// Flash attention per head, fp32. One CTA = 64 query rows x one head.
// Online softmax kept in registers (each S-row owned by 16 consecutive lanes
// -> width-16 shfl reductions). P^T reuses the K smem buffer.
// Smem: exactly 48KB (3 x 64x64 fp32), XOR swizzle phys = col ^ (k & 0x3C).
// ---------------------------------------------------------------------------
__global__ __launch_bounds__(256) void attn_kernel(
    const float* __restrict__ Kh, const float* __restrict__ Qh,
    const float* __restrict__ Vh, float* __restrict__ cat)
{
    __shared__ float QsT[64 * 64];
    __shared__ float KsT[64 * 64];   // reused for P^T
    __shared__ float Vs[64 * 64];

    const int t  = threadIdx.x;
    const int tx = t & 15;
    const int ty = t >> 4;
    const int qb = blockIdx.x;
    const int h  = blockIdx.y;

    const float* Qg = Qh + ((long long)h * S_LEN + qb * 64) * DH;
    const float* Kg = Kh + (long long)h * S_LEN * DH;
    const float* Vg = Vh + (long long)h * S_LEN * DH;

    // Load + scale Q tile, transposed into smem: QsT[d][qrow]
#pragma unroll
    for (int r = 0; r < 4; r++) {
        const int fidx = t + r * 256;         // float4 index 0..1023
        const int row  = fidx >> 4;
        const int c4   = (fidx & 15) << 2;
        float4 v = *(const float4*)(Qg + row * DH + c4);
        const float sc = 0.125f;              // 1/sqrt(64)
        QsT[(c4 + 0) * 64 + (row ^ ((c4 + 0) & 0x3C))] = v.x * sc;
        QsT[(c4 + 1) * 64 + (row ^ ((c4 + 1) & 0x3C))] = v.y * sc;
        QsT[(c4 + 2) * 64 + (row ^ ((c4 + 2) & 0x3C))] = v.z * sc;
        QsT[(c4 + 3) * 64 + (row ^ ((c4 + 3) & 0x3C))] = v.w * sc;
    }

    float o[4][4] = {};
    float m_i[4], l_i[4];
#pragma unroll
    for (int i = 0; i < 4; i++) { m_i[i] = -INFINITY; l_i[i] = 0.0f; }

    for (int kb = 0; kb < S_LEN / 64; kb++) {
        __syncthreads();   // previous PV reads done; Q stores visible (1st iter)
        // Load K tile (transposed+swizzled) and V tile (natural, float4)
#pragma unroll
        for (int r = 0; r < 4; r++) {
            const int fidx = t + r * 256;
            const int row  = fidx >> 4;
            const int c4   = (fidx & 15) << 2;
            float4 kv = *(const float4*)(Kg + (kb * 64 + row) * DH + c4);
            KsT[(c4 + 0) * 64 + (row ^ ((c4 + 0) & 0x3C))] = kv.x;
            KsT[(c4 + 1) * 64 + (row ^ ((c4 + 1) & 0x3C))] = kv.y;
            KsT[(c4 + 2) * 64 + (row ^ ((c4 + 2) & 0x3C))] = kv.z;
            KsT[(c4 + 3) * 64 + (row ^ ((c4 + 3) & 0x3C))] = kv.w;
            float4 vv = *(const float4*)(Vg + (kb * 64 + row) * DH + c4);
            *(float4*)&Vs[row * 64 + c4] = vv;
        }
        __syncthreads();

        // S = (Q*scale) @ K^T   (s[i][j]: qrow=4ty+i, kcol=4tx+j)
        float s[4][4] = {};
#pragma unroll
        for (int kk = 0; kk < 64; kk++) {
            const int sw = kk & 0x3C;
            float4 a = *(const float4*)&QsT[kk * 64 + ((4 * ty) ^ sw)];
            float4 b = *(const float4*)&KsT[kk * 64 + ((4 * tx) ^ sw)];
            float ar[4] = {a.x, a.y, a.z, a.w};
            float br[4] = {b.x, b.y, b.z, b.w};
#pragma unroll
            for (int i = 0; i < 4; i++)
#pragma unroll
                for (int j = 0; j < 4; j++)
                    s[i][j] = fmaf(ar[i], br[j], s[i][j]);
        }

        // Online softmax update (register-resident; rows replicated x16 lanes)
#pragma unroll
        for (int i = 0; i < 4; i++) {
            float tm = fmaxf(fmaxf(s[i][0], s[i][1]), fmaxf(s[i][2], s[i][3]));
#pragma unroll
            for (int msk = 1; msk < 16; msk <<= 1)
                tm = fmaxf(tm, __shfl_xor_sync(0xffffffffu, tm, msk, 16));
            const float mn = fmaxf(m_i[i], tm);
            const float al = __expf(m_i[i] - mn);
            m_i[i] = mn;
            float rs = 0.0f;
#pragma unroll
            for (int j = 0; j < 4; j++) {
                s[i][j] = __expf(s[i][j] - mn);
                rs += s[i][j];
            }
#pragma unroll
            for (int msk = 1; msk < 16; msk <<= 1)
                rs += __shfl_xor_sync(0xffffffffu, rs, msk, 16);
            l_i[i] = l_i[i] * al + rs;
#pragma unroll
            for (int j = 0; j < 4; j++) o[i][j] *= al;
        }

        __syncthreads();   // all S-phase reads of KsT done
        // Store P^T into KsT: logical PT[kcol][qrow]
#pragma unroll
        for (int j = 0; j < 4; j++) {
            const int kc = 4 * tx + j;
            const int sw = kc & 0x3C;
#pragma unroll
            for (int i = 0; i < 4; i++)
                KsT[kc * 64 + ((4 * ty + i) ^ sw)] = s[i][j];
        }
        __syncthreads();

        // O += P @ V  (o[i][j]: qrow=4ty+i, dcol=4tx+j)
#pragma unroll
        for (int kr = 0; kr < 64; kr++) {
            const int sw = kr & 0x3C;
            float4 a = *(const float4*)&KsT[kr * 64 + ((4 * ty) ^ sw)];
            float4 b = *(const float4*)&Vs[kr * 64 + 4 * tx];
            float ar[4] = {a.x, a.y, a.z, a.w};
            float br[4] = {b.x, b.y, b.z, b.w};
#pragma unroll
            for (int i = 0; i < 4; i++)
#pragma unroll
                for (int j = 0; j < 4; j++)
                    o[i][j] = fmaf(ar[i], br[j], o[i][j]);
        }
    }

    // Epilogue: normalize and write cat[s, h*64 + d]
#pragma unroll
    for (int i = 0; i < 4; i++) {
        const float inv = 1.0f / l_i[i];
        const int row = qb * 64 + 4 * ty + i;
        float4 w = make_float4(o[i][0] * inv, o[i][1] * inv,
                               o[i][2] * inv, o[i][3] * inv);
        *(float4*)&cat[(long long)row * EMB + h * DH + 4 * tx] = w;
    }
}

// ---------------------------------------------------------------------------
// Row LayerNorm: one block per row, 256 threads x float4.
// ---------------------------------------------------------------------------
__global__ __launch_bounds__(256) void ln_kernel(
    const float* __restrict__ Y, const float* __restrict__ gamma,
    const float* __restrict__ beta, float* __restrict__ out)
{
    __shared__ float red1[8], red2[8];
    __shared__ float tot[2];
    const int row = blockIdx.x;
    const int t = threadIdx.x;

    float4 v = *(const float4*)(Y + (long long)row * EMB + 4 * t);
    float s1 = v.x + v.y + v.z + v.w;
    float s2 = v.x * v.x + v.y * v.y + v.z * v.z + v.w * v.w;
#pragma unroll
    for (int o_ = 16; o_ > 0; o_ >>= 1) {
        s1 += __shfl_xor_sync(0xffffffffu, s1, o_);
        s2 += __shfl_xor_sync(0xffffffffu, s2, o_);
    }
    const int wid = t >> 5, lane = t & 31;
    if (lane == 0) { red1[wid] = s1; red2[wid] = s2; }
    __syncthreads();
    if (t == 0) {
        float a = 0.0f, b = 0.0f;
#pragma unroll
        for (int i = 0; i < 8; i++) { a += red1[i]; b += red2[i]; }
        tot[0] = a; tot[1] = b;
    }
    __syncthreads();
    const float mu   = tot[0] * (1.0f / EMB);
    const float var  = tot[1] * (1.0f / EMB) - mu * mu;
    const float rstd = rsqrtf(var + 1e-5f);

    float4 g  = *(const float4*)&gamma[4 * t];
    float4 bb = *(const float4*)&beta[4 * t];
    float4 o4;
    o4.x = (v.x - mu) * rstd * g.x + bb.x;
    o4.y = (v.y - mu) * rstd * g.y + bb.y;
    o4.z = (v.z - mu) * rstd * g.z + bb.z;
    o4.w = (v.w - mu) * rstd * g.w + bb.w;
    *(float4*)&out[(long long)row * EMB + 4 * t] = o4;
}

// ---------------------------------------------------------------------------
extern "C" void kernel_launch(void* const* d_in, const int* in_sizes, int n_in,
                              void* d_out, int out_size)
{
    const float* x     = (const float*)d_in[0];
    const float* Wk    = (const float*)d_in[1];
    const float* Wq    = (const float*)d_in[2];
    const float* Wv    = (const float*)d_in[3];
    const float* hWk   = (const float*)d_in[4];
    const float* hbk   = (const float*)d_in[5];
    const float* hWv   = (const float*)d_in[6];
    const float* hbv   = (const float*)d_in[7];
    const float* hWq   = (const float*)d_in[8];
    const float* hbq   = (const float*)d_in[9];
    const float* Wo    = (const float*)d_in[10];
    const float* bo    = (const float*)d_in[11];
    const float* gamma = (const float*)d_in[12];
    const float* beta  = (const float*)d_in[13];
    float* out = (float*)d_out;

    float *pKQV, *pH, *pcat, *py;
    cudaGetSymbolAddress((void**)&pKQV, g_KQV);
    cudaGetSymbolAddress((void**)&pH,   g_H);
    cudaGetSymbolAddress((void**)&pcat, g_cat);
    cudaGetSymbolAddress((void**)&py,   g_y);

    const long long SD  = (long long)S_LEN * DH;       // 131072
    const long long HSD = (long long)NH * S_LEN * DH;  // 2097152
    dim3 blk(256);

    // Stage 1: shared projections  K,Q,V = x @ W^T   [2048,64]
    gemm_abt<<<dim3(32, 1, 1), blk>>>(x, Wk, nullptr, nullptr, pKQV + 0 * SD,
                                      S_LEN, DH, EMB, 0, 0, 0);
    gemm_abt<<<dim3(32, 1, 1), blk>>>(x, Wq, nullptr, nullptr, pKQV + 1 * SD,
                                      S_LEN, DH, EMB, 0, 0, 0);
    gemm_abt<<<dim3(32, 1, 1), blk>>>(x, Wv, nullptr, nullptr, pKQV + 2 * SD,
                                      S_LEN, DH, EMB, 0, 0, 0);

    // Stage 2: per-head linears  Xh[h] = X @ hW[h]^T + hb[h]
    gemm_abt<<<dim3(32, 1, NH), blk>>>(pKQV + 0 * SD, hWk, hbk, nullptr, pH + 0 * HSD,
                                       S_LEN, DH, DH, DH * DH, DH, SD);
    gemm_abt<<<dim3(32, 1, NH), blk>>>(pKQV + 1 * SD, hWq, hbq, nullptr, pH + 1 * HSD,
                                       S_LEN, DH, DH, DH * DH, DH, SD);
    gemm_abt<<<dim3(32, 1, NH), blk>>>(pKQV + 2 * SD, hWv, hbv, nullptr, pH + 2 * HSD,
                                       S_LEN, DH, DH, DH * DH, DH, SD);

    // Stage 3: flash attention -> cat layout [S, H*D]
    attn_kernel<<<dim3(32, NH), blk>>>(pH + 0 * HSD, pH + 1 * HSD, pH + 2 * HSD, pcat);

    // Stage 4: out = cat @ Wo^T + bo + x
    gemm_abt<<<dim3(32, 16, 1), blk>>>(pcat, Wo, bo, x, py,
                                       S_LEN, EMB, EMB, 0, 0, 0);

    // Stage 5: LayerNorm
    ln_kernel<<<S_LEN, 256>>>(py, gamma, beta, out);
}

// round 3
// speedup vs baseline: 2.4588x; 2.4588x over previous
#include <cuda_runtime.h>
#include <math.h>
#include <stdint.h>

#define S_LEN 2048
#define EMB   1024
#define DH    64
#define NH    16

// Scratch (device globals: no allocations allowed)
__device__ float g_KQV[3 * S_LEN * DH];            // K,Q,V after shared projection
__device__ float g_H[3 * NH * S_LEN * DH];         // Kh,Qh,Vh per head
__device__ float g_cat[S_LEN * EMB];               // concatenated attention output
__device__ float g_y[S_LEN * EMB];                 // pre-LayerNorm

// ===========================================================================
// Helpers (baseline PTX only: mma.sync / ldmatrix — no sm_103a-specific ops)
// ===========================================================================
__device__ __forceinline__ uint32_t smem_u32(const void* p) {
    uint32_t a;
    asm("{ .reg .u64 t; cvta.to.shared.u64 t, %1; cvt.u32.u64 %0, t; }"
        : "=r"(a) : "l"(p));
    return a;
}

// SW128-style swizzle on byte offsets within a 128B-row tile
__device__ __forceinline__ uint32_t swz(uint32_t off) {
    return off ^ (((off >> 7) & 7u) << 4);
}

__device__ __forceinline__ float trunc16f(float x) {
    return __uint_as_float(__float_as_uint(x) & 0xffff0000u);
}

// pack top-16 bits (bf16 truncation) of two floats: low half = x, high = y
__device__ __forceinline__ uint32_t pack_hi2(float x, float y) {
    uint32_t r;
    asm("prmt.b32 %0, %1, %2, 0x7632;"
        : "=r"(r) : "r"(__float_as_uint(x)), "r"(__float_as_uint(y)));
    return r;
}

// rounded bf16x2 pack: low half = lo_elem, high = hi_elem
__device__ __forceinline__ uint32_t cvt2bf(float hi_elem, float lo_elem) {
    uint32_t r;
    asm("cvt.rn.bf16x2.f32 %0, %1, %2;" : "=r"(r) : "f"(hi_elem), "f"(lo_elem));
    return r;
}

// fast 2^x on FMA/ALU pipes (avoids MUFU). x <= ~30; clamped below at -126.
__device__ __forceinline__ float fex2(float x) {
    x = fmaxf(x, -126.0f);
    float n = rintf(x);
    float f = x - n;
    float p = fmaf(0.0096181f, f, 0.0555036f);
    p = fmaf(p, f, 0.2402264f);
    p = fmaf(p, f, 0.6931472f);
    p = fmaf(p, f, 1.0f);
    int e = (int)n;
    return p * __int_as_float((e + 127) << 23);
}

__device__ __forceinline__ void mma_bf16(float c[4],
    uint32_t a0, uint32_t a1, uint32_t a2, uint32_t a3,
    uint32_t b0, uint32_t b1)
{
    asm volatile(
        "mma.sync.aligned.m16n8k16.row.col.f32.bf16.bf16.f32 "
        "{%0,%1,%2,%3}, {%4,%5,%6,%7}, {%8,%9}, {%0,%1,%2,%3};"
        : "+f"(c[0]), "+f"(c[1]), "+f"(c[2]), "+f"(c[3])
        : "r"(a0), "r"(a1), "r"(a2), "r"(a3), "r"(b0), "r"(b1));
}

__device__ __forceinline__ void ldsm_x4(uint32_t r[4], uint32_t addr) {
    asm volatile("ldmatrix.sync.aligned.m8n8.x4.shared.b16 {%0,%1,%2,%3}, [%4];"
                 : "=r"(r[0]), "=r"(r[1]), "=r"(r[2]), "=r"(r[3]) : "r"(addr));
}
__device__ __forceinline__ void ldsm_x4t(uint32_t r[4], uint32_t addr) {
    asm volatile("ldmatrix.sync.aligned.m8n8.x4.trans.shared.b16 {%0,%1,%2,%3}, [%4];"
                 : "=r"(r[0]), "=r"(r[1]), "=r"(r[2]), "=r"(r[3]) : "r"(addr));
}

// Stage a 128x64 fp32 tile (row stride ldg) into hi/lo bf16 smem tiles
// (128B rows, swizzled). 256 threads.
__device__ __forceinline__ void stage128(char* dhi, char* dlo,
    const float* __restrict__ g, int ldg, float sc, int tid)
{
#pragma unroll
    for (int i4 = tid; i4 < 2048; i4 += 256) {
        const int r = i4 >> 4, c4 = (i4 & 15) << 2;
        float4 v = *(const float4*)(g + (long long)r * ldg + c4);
        v.x *= sc; v.y *= sc; v.z *= sc; v.w *= sc;
        uint32_t h0 = pack_hi2(v.x, v.y);
        uint32_t h1 = pack_hi2(v.z, v.w);
        float lx = v.x - trunc16f(v.x);
        float ly = v.y - trunc16f(v.y);
        float lz = v.z - trunc16f(v.z);
        float lw = v.w - trunc16f(v.w);
        uint32_t l0 = cvt2bf(ly, lx);
        uint32_t l1 = cvt2bf(lw, lz);
        const uint32_t off = swz((uint32_t)(r * 128 + c4 * 2));
        *(uint2*)(dhi + off) = make_uint2(h0, h1);
        *(uint2*)(dlo + off) = make_uint2(l0, l1);
    }
}

// ===========================================================================
// Stage 1: K/Q/V shared projections (SIMT fp32). 64x64 tile, K=1024, z=3.
// ===========================================================================
__global__ __launch_bounds__(256) void gemm_qkv2(
    const float* __restrict__ A,
    const float* __restrict__ W0, const float* __restrict__ W1,
    const float* __restrict__ W2, float* __restrict__ C)
{
    __shared__ float AsT[16 * 64];
    __shared__ float BsT[16 * 64];
    const int t = threadIdx.x;
    const int tx = t & 15, ty = t >> 4;
    const int bm = blockIdx.x * 64;
    const int z = blockIdx.z;
    const float* W = (z == 0) ? W0 : ((z == 1) ? W1 : W2);
    float* Cz = C + (long long)z * S_LEN * DH;

    const int lm = t >> 2, k0 = (t & 3) << 2;
    float acc[4][4] = {};

    for (int kc = 0; kc < EMB; kc += 16) {
        float4 av = *(const float4*)(A + (long long)(bm + lm) * EMB + kc + k0);
        float4 bv = *(const float4*)(W + (long long)lm * EMB + kc + k0);
        __syncthreads();
        {
            float a4[4] = {av.x, av.y, av.z, av.w};
            float b4[4] = {bv.x, bv.y, bv.z, bv.w};
#pragma unroll
            for (int i = 0; i < 4; i++) {
                const int sw = (k0 + i) & 12;
                AsT[(k0 + i) * 64 + (lm ^ sw)] = a4[i];
                BsT[(k0 + i) * 64 + (lm ^ sw)] = b4[i];
            }
        }
        __syncthreads();
#pragma unroll
        for (int kk = 0; kk < 16; kk++) {
            const int sw = kk & 12;
            float4 a = *(const float4*)&AsT[kk * 64 + ((4 * ty) ^ sw)];
            float4 b = *(const float4*)&BsT[kk * 64 + ((4 * tx) ^ sw)];
            float ar[4] = {a.x, a.y, a.z, a.w};
            float br[4] = {b.x, b.y, b.z, b.w};
#pragma unroll
            for (int i = 0; i < 4; i++)
#pragma unroll
                for (int j = 0; j < 4; j++)
                    acc[i][j] = fmaf(ar[i], br[j], acc[i][j]);
        }
    }
#pragma unroll
    for (int i = 0; i < 4; i++) {
        const int row = bm + 4 * ty + i;
        *(float4*)&Cz[(long long)row * DH + 4 * tx] =
            make_float4(acc[i][0], acc[i][1], acc[i][2], acc[i][3]);
    }
}

// ===========================================================================
// Stage 2: per-head linears (SIMT fp32), z in [0,48).
// ===========================================================================
__global__ __launch_bounds__(256) void gemm_heads(
    const float* __restrict__ X,
    const float* __restrict__ Wk_, const float* __restrict__ bk_,
    const float* __restrict__ Wq_, const float* __restrict__ bq_,
    const float* __restrict__ Wv_, const float* __restrict__ bv_,
    float* __restrict__ Out)
{
    __shared__ float AsT[16 * 64];
    __shared__ float BsT[16 * 64];
    const int t = threadIdx.x;
    const int tx = t & 15, ty = t >> 4;
    const int bm = blockIdx.x * 64;
    const int z = blockIdx.z;
    const int tz = z >> 4, hh = z & 15;

    const float* A = X + (long long)tz * S_LEN * DH;
    const float* W = ((tz == 0) ? Wk_ : ((tz == 1) ? Wq_ : Wv_)) + hh * DH * DH;
    const float* bb = ((tz == 0) ? bk_ : ((tz == 1) ? bq_ : bv_)) + hh * DH;
    float* C = Out + ((long long)tz * NH + hh) * S_LEN * DH;

    const int lm = t >> 2, k0 = (t & 3) << 2;
    float acc[4][4] = {};

    for (int kc = 0; kc < DH; kc += 16) {
        float4 av = *(const float4*)(A + (long long)(bm + lm) * DH + kc + k0);
        float4 bv4 = *(const float4*)(W + (long long)lm * DH + kc + k0);
        __syncthreads();
        {
            float a4[4] = {av.x, av.y, av.z, av.w};
            float b4[4] = {bv4.x, bv4.y, bv4.z, bv4.w};
#pragma unroll
            for (int i = 0; i < 4; i++) {
                const int sw = (k0 + i) & 12;
                AsT[(k0 + i) * 64 + (lm ^ sw)] = a4[i];
                BsT[(k0 + i) * 64 + (lm ^ sw)] = b4[i];
            }
        }
        __syncthreads();
#pragma unroll
        for (int kk = 0; kk < 16; kk++) {
            const int sw = kk & 12;
            float4 a = *(const float4*)&AsT[kk * 64 + ((4 * ty) ^ sw)];
            float4 b = *(const float4*)&BsT[kk * 64 + ((4 * tx) ^ sw)];
            float ar[4] = {a.x, a.y, a.z, a.w};
            float br[4] = {b.x, b.y, b.z, b.w};
#pragma unroll
            for (int i = 0; i < 4; i++)
#pragma unroll
                for (int j = 0; j < 4; j++)
                    acc[i][j] = fmaf(ar[i], br[j], acc[i][j]);
        }
    }
    float4 bias4 = *(const float4*)&bb[4 * tx];
#pragma unroll
    for (int i = 0; i < 4; i++) {
        const int row = bm + 4 * ty + i;
        *(float4*)&C[(long long)row * DH + 4 * tx] =
            make_float4(acc[i][0] + bias4.x, acc[i][1] + bias4.y,
                        acc[i][2] + bias4.z, acc[i][3] + bias4.w);
    }
}

// ===========================================================================
// Stage 3: flash attention on HMMA (mma.sync bf16 x3 split, fp32 accum).
// CTA = 128 Q rows x 1 head, 8 warps (warp w -> Q rows 16w..16w+15).
// Smem 64KB: K hi/lo + V hi/lo (128x64 bf16 each, 128B rows, swizzled).
// Softmax row-resident: each thread owns rows (16w + l/4) and (+8), reduced
// over the 4-lane quad with xor-shuffles; exp2 via FMA-pipe polynomial.
// ===========================================================================
#define ATT_SMEM 65536

__global__ __launch_bounds__(256, 2) void attn_mma(
    const float* __restrict__ Kh, const float* __restrict__ Qh,
    const float* __restrict__ Vh, float* __restrict__ cat)
{
    extern __shared__ char sm[];
    char* KHI = sm;
    char* KLO = sm + 16384;
    char* VHI = sm + 32768;
    char* VLO = sm + 49152;
    const uint32_t sKHI = smem_u32(KHI), sKLO = smem_u32(KLO);
    const uint32_t sVHI = smem_u32(VHI), sVLO = smem_u32(VLO);

    const int tid = threadIdx.x;
    const int w = tid >> 5, l = tid & 31;
    const int qb = blockIdx.x, h = blockIdx.y;
    const int rl = l & 7, mi = l >> 3;

    const float* Qg = Qh + ((long long)h * S_LEN + qb * 128) * DH;
    const float* Kg = Kh + (long long)h * S_LEN * DH;
    const float* Vg = Vh + (long long)h * S_LEN * DH;

    const float SC = 0.125f * 1.44269504088896340736f;  // 1/sqrt(D) * log2(e)

    // ---- Q tile -> smem (reuse K buffers) -> a-fragments in registers
    stage128(KHI, KLO, Qg, DH, SC, tid);
    __syncthreads();
    uint32_t aqh[4][4], aql[4][4];
    {
        const int aRow = 16 * w + rl + ((mi & 1) ? 8 : 0);
        const int cAdd = (mi & 2) ? 8 : 0;
#pragma unroll
        for (int s = 0; s < 4; s++) {
            const uint32_t off = swz((uint32_t)(aRow * 128 + (16 * s + cAdd) * 2));
            ldsm_x4(aqh[s], sKHI + off);
            ldsm_x4(aql[s], sKLO + off);
        }
    }
    __syncthreads();

    float o[8][4];
#pragma unroll
    for (int j = 0; j < 8; j++)
#pragma unroll
        for (int k = 0; k < 4; k++) o[j][k] = 0.0f;
    float m0 = -1e30f, m1 = -1e30f, l0 = 0.0f, l1 = 0.0f;

    for (int kb = 0; kb < S_LEN / 128; kb++) {
        stage128(KHI, KLO, Kg + (long long)kb * 128 * DH, DH, 1.0f, tid);
        stage128(VHI, VLO, Vg + (long long)kb * 128 * DH, DH, 1.0f, tid);
        __syncthreads();

#pragma unroll
        for (int hf = 0; hf < 2; hf++) {
            // ---- S = Q @ K^T (16 x 64 per warp), bf16x3
            float s[8][4];
#pragma unroll
            for (int j = 0; j < 8; j++)
#pragma unroll
                for (int k = 0; k < 4; k++) s[j][k] = 0.0f;

#pragma unroll
            for (int jj = 0; jj < 4; jj++) {
                const int nrow = hf * 64 + 16 * jj + rl + ((mi & 2) ? 8 : 0);
#pragma unroll
                for (int ks = 0; ks < 4; ks++) {
                    const int kcol = 16 * ks + ((mi & 1) ? 8 : 0);
                    const uint32_t off = swz((uint32_t)(nrow * 128 + kcol * 2));
                    uint32_t bh[4], bl[4];
                    ldsm_x4(bh, sKHI + off);
                    ldsm_x4(bl, sKLO + off);
                    mma_bf16(s[2 * jj], aqh[ks][0], aqh[ks][1], aqh[ks][2], aqh[ks][3], bh[0], bh[1]);
                    mma_bf16(s[2 * jj], aqh[ks][0], aqh[ks][1], aqh[ks][2], aqh[ks][3], bl[0], bl[1]);
                    mma_bf16(s[2 * jj], aql[ks][0], aql[ks][1], aql[ks][2], aql[ks][3], bh[0], bh[1]);
                    mma_bf16(s[2 * jj + 1], aqh[ks][0], aqh[ks][1], aqh[ks][2], aqh[ks][3], bh[2], bh[3]);
                    mma_bf16(s[2 * jj + 1], aqh[ks][0], aqh[ks][1], aqh[ks][2], aqh[ks][3], bl[2], bl[3]);
                    mma_bf16(s[2 * jj + 1], aql[ks][0], aql[ks][1], aql[ks][2], aql[ks][3], bh[2], bh[3]);
                }
            }

            // ---- online softmax (exp2 domain, FMA-pipe poly)
            float rm0 = -1e30f, rm1 = -1e30f;
#pragma unroll
            for (int j = 0; j < 8; j++) {
                rm0 = fmaxf(rm0, fmaxf(s[j][0], s[j][1]));
                rm1 = fmaxf(rm1, fmaxf(s[j][2], s[j][3]));
            }
            rm0 = fmaxf(rm0, __shfl_xor_sync(0xffffffffu, rm0, 1));
            rm0 = fmaxf(rm0, __shfl_xor_sync(0xffffffffu, rm0, 2));
            rm1 = fmaxf(rm1, __shfl_xor_sync(0xffffffffu, rm1, 1));
            rm1 = fmaxf(rm1, __shfl_xor_sync(0xffffffffu, rm1, 2));
            const float mn0 = fmaxf(m0, rm0), mn1 = fmaxf(m1, rm1);
            const float al0 = fex2(m0 - mn0), al1 = fex2(m1 - mn1);
            m0 = mn0; m1 = mn1;

            float sum0 = 0.0f, sum1 = 0.0f;
#pragma unroll
            for (int j = 0; j < 8; j++) {
                s[j][0] = fex2(s[j][0] - mn0);
                s[j][1] = fex2(s[j][1] - mn0);
                s[j][2] = fex2(s[j][2] - mn1);
                s[j][3] = fex2(s[j][3] - mn1);
                sum0 += s[j][0] + s[j][1];
                sum1 += s[j][2] + s[j][3];
            }
            sum0 += __shfl_xor_sync(0xffffffffu, sum0, 1);
            sum0 += __shfl_xor_sync(0xffffffffu, sum0, 2);
            sum1 += __shfl_xor_sync(0xffffffffu, sum1, 1);
            sum1 += __shfl_xor_sync(0xffffffffu, sum1, 2);
            l0 = l0 * al0 + sum0;
            l1 = l1 * al1 + sum1;
#pragma unroll
            for (int j = 0; j < 8; j++) {
                o[j][0] *= al0; o[j][1] *= al0;
                o[j][2] *= al1; o[j][3] *= al1;
            }

            // ---- pack P into a-fragments (hi trunc + lo residual)
            uint32_t pah[4][4], pal[4][4];
#pragma unroll
            for (int ks = 0; ks < 4; ks++) {
                const int j0 = 2 * ks, j1 = 2 * ks + 1;
                pah[ks][0] = pack_hi2(s[j0][0], s[j0][1]);
                pah[ks][1] = pack_hi2(s[j0][2], s[j0][3]);
                pah[ks][2] = pack_hi2(s[j1][0], s[j1][1]);
                pah[ks][3] = pack_hi2(s[j1][2], s[j1][3]);
                pal[ks][0] = cvt2bf(s[j0][1] - trunc16f(s[j0][1]), s[j0][0] - trunc16f(s[j0][0]));
                pal[ks][1] = cvt2bf(s[j0][3] - trunc16f(s[j0][3]), s[j0][2] - trunc16f(s[j0][2]));
                pal[ks][2] = cvt2bf(s[j1][1] - trunc16f(s[j1][1]), s[j1][0] - trunc16f(s[j1][0]));
                pal[ks][3] = cvt2bf(s[j1][3] - trunc16f(s[j1][3]), s[j1][2] - trunc16f(s[j1][2]));
            }

            // ---- O += P @ V, bf16x3
#pragma unroll
            for (int jj = 0; jj < 4; jj++) {
                const int ncol = 16 * jj + ((mi & 2) ? 8 : 0);
#pragma unroll
                for (int ks = 0; ks < 4; ks++) {
                    const int krow = hf * 64 + 16 * ks + rl + ((mi & 1) ? 8 : 0);
                    const uint32_t off = swz((uint32_t)(krow * 128 + ncol * 2));
                    uint32_t vh[4], vl[4];
                    ldsm_x4t(vh, sVHI + off);
                    ldsm_x4t(vl, sVLO + off);
                    mma_bf16(o[2 * jj], pah[ks][0], pah[ks][1], pah[ks][2], pah[ks][3], vh[0], vh[1]);
                    mma_bf16(o[2 * jj], pah[ks][0], pah[ks][1], pah[ks][2], pah[ks][3], vl[0], vl[1]);
                    mma_bf16(o[2 * jj], pal[ks][0], pal[ks][1], pal[ks][2], pal[ks][3], vh[0], vh[1]);
                    mma_bf16(o[2 * jj + 1], pah[ks][0], pah[ks][1], pah[ks][2], pah[ks][3], vh[2], vh[3]);
                    mma_bf16(o[2 * jj + 1], pah[ks][0], pah[ks][1], pah[ks][2], pah[ks][3], vl[2], vl[3]);
                    mma_bf16(o[2 * jj + 1], pal[ks][0], pal[ks][1], pal[ks][2], pal[ks][3], vh[2], vh[3]);
                }
            }
        }
        __syncthreads();
    }

    // ---- epilogue: normalize, write to cat[row][h*64 + col]
    const float i0 = 1.0f / l0, i1 = 1.0f / l1;
    const int r0 = qb * 128 + 16 * w + (l >> 2);
#pragma unroll
    for (int j = 0; j < 8; j++) {
        const int col = h * DH + 8 * j + 2 * (l & 3);
        *(float2*)&cat[(long long)r0 * EMB + col] =
            make_float2(o[j][0] * i0, o[j][1] * i0);
        *(float2*)&cat[(long long)(r0 + 8) * EMB + col] =
            make_float2(o[j][2] * i1, o[j][3] * i1);
    }
}

// ===========================================================================
// Stage 4: out = cat @ Wo^T + bo + x, HMMA bf16x3. CTA 128x128, 8 warps.
// ===========================================================================
#define GM_SMEM 65536

__global__ __launch_bounds__(256) void gemm_mma(
    const float* __restrict__ A, const float* __restrict__ B,
    const float* __restrict__ bias, const float* __restrict__ res,
    float* __restrict__ C)
{
    extern __shared__ char sm[];
    char* AH = sm;
    char* AL = sm + 16384;
    char* BH = sm + 32768;
    char* BL = sm + 49152;
    const uint32_t sAH = smem_u32(AH), sAL = smem_u32(AL);
    const uint32_t sBH = smem_u32(BH), sBL = smem_u32(BL);

    const int tid = threadIdx.x;
    const int w = tid >> 5, l = tid & 31;
    const int rl = l & 7, mi = l >> 3;
    const int wm = w & 1, wn = w >> 1;
    const int bm = blockIdx.x * 128, bn = blockIdx.y * 128;

    float c[4][4][4];
#pragma unroll
    for (int a = 0; a < 4; a++)
#pragma unroll
        for (int b = 0; b < 4; b++)
#pragma unroll
            for (int k = 0; k < 4; k++) c[a][b][k] = 0.0f;

    for (int kc = 0; kc < EMB; kc += 64) {
        stage128(AH, AL, A + (long long)bm * EMB + kc, EMB, 1.0f, tid);
        stage128(BH, BL, B + (long long)bn * EMB + kc, EMB, 1.0f, tid);
        __syncthreads();

#pragma unroll
        for (int ks = 0; ks < 4; ks++) {
            uint32_t ah[4][4], al_[4][4];
            const int aRow0 = 64 * wm + rl + ((mi & 1) ? 8 : 0);
            const int aCAdd = (mi & 2) ? 8 : 0;
#pragma unroll
            for (int mt = 0; mt < 4; mt++) {
                const uint32_t off =
                    swz((uint32_t)((aRow0 + 16 * mt) * 128 + (16 * ks + aCAdd) * 2));
                ldsm_x4(ah[mt], sAH + off);
                ldsm_x4(al_[mt], sAL + off);
            }
            uint32_t bhf[4][2], blf[4][2];
            const int bRowAdd = (mi & 2) ? 8 : 0;
            const int bCol = 16 * ks + ((mi & 1) ? 8 : 0);
#pragma unroll
            for (int jj = 0; jj < 2; jj++) {
                const int nrow = 32 * wn + 16 * jj + rl + bRowAdd;
                const uint32_t off = swz((uint32_t)(nrow * 128 + bCol * 2));
                uint32_t t4[4], u4[4];
                ldsm_x4(t4, sBH + off);
                ldsm_x4(u4, sBL + off);
                bhf[2 * jj][0] = t4[0]; bhf[2 * jj][1] = t4[1];
                bhf[2 * jj + 1][0] = t4[2]; bhf[2 * jj + 1][1] = t4[3];
                blf[2 * jj][0] = u4[0]; blf[2 * jj][1] = u4[1];
                blf[2 * jj + 1][0] = u4[2]; blf[2 * jj + 1][1] = u4[3];
            }
#pragma unroll
            for (int mt = 0; mt < 4; mt++)
#pragma unroll
                for (int nt = 0; nt < 4; nt++) {
                    mma_bf16(c[mt][nt], ah[mt][0], ah[mt][1], ah[mt][2], ah[mt][3],
                             bhf[nt][0], bhf[nt][1]);
                    mma_bf16(c[mt][nt], ah[mt][0], ah[mt][1], ah[mt][2], ah[mt][3],
                             blf[nt][0], blf[nt][1]);
                    mma_bf16(c[mt][nt], al_[mt][0], al_[mt][1], al_[mt][2], al_[mt][3],
                             bhf[nt][0], bhf[nt][1]);
                }
        }
        __syncthreads();
    }

    // epilogue: + bias + residual
#pragma unroll
    for (int mt = 0; mt < 4; mt++) {
        const int row0 = bm + 64 * wm + 16 * mt + (l >> 2);
#pragma unroll
        for (int nt = 0; nt < 4; nt++) {
            const int col = bn + 32 * wn + 8 * nt + 2 * (l & 3);
            float2 bb = *(const float2*)&bias[col];
            float2 r0v = *(const float2*)&res[(long long)row0 * EMB + col];
            float2 r1v = *(const float2*)&res[(long long)(row0 + 8) * EMB + col];
            *(float2*)&C[(long long)row0 * EMB + col] =
                make_float2(c[mt][nt][0] + bb.x + r0v.x, c[mt][nt][1] + bb.y + r0v.y);
            *(float2*)&C[(long long)(row0 + 8) * EMB + col] =
                make_float2(c[mt][nt][2] + bb.x + r1v.x, c[mt][nt][3] + bb.y + r1v.y);
        }
    }
}

// ---------------------------------------------------------------------------
__global__ __launch_bounds__(256) void ln_kernel(
    const float* __restrict__ Y, const float* __restrict__ gamma,
    const float* __restrict__ beta, float* __restrict__ out)
{
    __shared__ float red1[8], red2[8];
    __shared__ float tot[2];
    const int row = blockIdx.x;
    const int t = threadIdx.x;

    float4 v = *(const float4*)(Y + (long long)row * EMB + 4 * t);
    float s1 = v.x + v.y + v.z + v.w;
    float s2 = v.x * v.x + v.y * v.y + v.z * v.z + v.w * v.w;
#pragma unroll
    for (int o_ = 16; o_ > 0; o_ >>= 1) {
        s1 += __shfl_xor_sync(0xffffffffu, s1, o_);
        s2 += __shfl_xor_sync(0xffffffffu, s2, o_);
    }
    const int wid = t >> 5, lane = t & 31;
    if (lane == 0) { red1[wid] = s1; red2[wid] = s2; }
    __syncthreads();
    if (t == 0) {
        float a = 0.0f, b = 0.0f;
#pragma unroll
        for (int i = 0; i < 8; i++) { a += red1[i]; b += red2[i]; }
        tot[0] = a; tot[1] = b;
    }
    __syncthreads();
    const float mu   = tot[0] * (1.0f / EMB);
    const float var  = tot[1] * (1.0f / EMB) - mu * mu;
    const float rstd = rsqrtf(var + 1e-5f);

    float4 g  = *(const float4*)&gamma[4 * t];
    float4 bb = *(const float4*)&beta[4 * t];
    float4 o4;
    o4.x = (v.x - mu) * rstd * g.x + bb.x;
    o4.y = (v.y - mu) * rstd * g.y + bb.y;
    o4.z = (v.z - mu) * rstd * g.z + bb.z;
    o4.w = (v.w - mu) * rstd * g.w + bb.w;
    *(float4*)&out[(long long)row * EMB + 4 * t] = o4;
}

__global__ void pad_kernel() {}

// ---------------------------------------------------------------------------
extern "C" void kernel_launch(void* const* d_in, const int* in_sizes, int n_in,
                              void* d_out, int out_size)
{
    const float* x     = (const float*)d_in[0];
    const float* Wk    = (const float*)d_in[1];
    const float* Wq    = (const float*)d_in[2];
    const float* Wv    = (const float*)d_in[3];
    const float* hWk   = (const float*)d_in[4];
    const float* hbk   = (const float*)d_in[5];
    const float* hWv   = (const float*)d_in[6];
    const float* hbv   = (const float*)d_in[7];
    const float* hWq   = (const float*)d_in[8];
    const float* hbq   = (const float*)d_in[9];
    const float* Wo    = (const float*)d_in[10];
    const float* bo    = (const float*)d_in[11];
    const float* gamma = (const float*)d_in[12];
    const float* beta  = (const float*)d_in[13];
    float* out = (float*)d_out;

    float *pKQV, *pH, *pcat, *py;
    cudaGetSymbolAddress((void**)&pKQV, g_KQV);
    cudaGetSymbolAddress((void**)&pH,   g_H);
    cudaGetSymbolAddress((void**)&pcat, g_cat);
    cudaGetSymbolAddress((void**)&py,   g_y);

    const long long HSD = (long long)NH * S_LEN * DH;

    cudaFuncSetAttribute(attn_mma, cudaFuncAttributeMaxDynamicSharedMemorySize, ATT_SMEM);
    cudaFuncSetAttribute(gemm_mma, cudaFuncAttributeMaxDynamicSharedMemorySize, GM_SMEM);

    // 1: K,Q,V = x @ W^T  (z: 0=K,1=Q,2=V)
    gemm_qkv2<<<dim3(32, 1, 3), 256>>>(x, Wk, Wq, Wv, pKQV);

    // 2: per-head linears (z = tz*16 + head; tz: 0=K,1=Q,2=V)
    gemm_heads<<<dim3(32, 1, 48), 256>>>(pKQV, hWk, hbk, hWq, hbq, hWv, hbv, pH);

    // pads so attention is the 6th launch (ncu -s 5 -c 1 captures it)
    pad_kernel<<<1, 32>>>();
    pad_kernel<<<1, 32>>>();
    pad_kernel<<<1, 32>>>();

    // 3: flash attention (HMMA bf16x3)
    attn_mma<<<dim3(16, NH), 256, ATT_SMEM>>>(
        pH + 0 * HSD, pH + 1 * HSD, pH + 2 * HSD, pcat);

    // 4: out = cat @ Wo^T + bo + x (HMMA bf16x3)
    gemm_mma<<<dim3(16, 8), 256, GM_SMEM>>>(pcat, Wo, bo, x, py);

    // 5: LayerNorm
    ln_kernel<<<S_LEN, 256>>>(py, gamma, beta, out);
}

// round 8
// speedup vs baseline: 2.7414x; 1.1149x over previous
#include <cuda_runtime.h>
#include <math.h>
#include <stdint.h>

#define S_LEN 2048
#define EMB   1024
#define DH    64
#define NH    16
#define TILE_B 16384   // one 128x64 bf16 tile, 128B rows, swizzled

// Scratch (device globals; no allocations allowed)
__device__ float   g_KQV[3 * S_LEN * DH];   // K,Q,V after shared projection (fp32)
__device__ uint8_t g_Hbf[3ull * NH * 16 * 2 * TILE_B];   // per-head K/Q/V bf16 hi+lo tiles
__device__ uint8_t g_catbf[16ull * NH * 2 * TILE_B];     // attention out bf16 tiles [rowblk][colblk]
__device__ uint8_t g_Wobf[8ull * 16 * 2 * TILE_B];       // Wo bf16 tiles [rowblk128][colblk64]
__device__ float   g_y[S_LEN * EMB];                     // pre-LayerNorm

// ===========================================================================
// Helpers (baseline PTX only — this build pipeline rejects sm_103a-specific ops)
// ===========================================================================
__device__ __forceinline__ uint32_t smem_u32(const void* p) {
    uint32_t a;
    asm("{ .reg .u64 t; cvta.to.shared.u64 t, %1; cvt.u32.u64 %0, t; }"
        : "=r"(a) : "l"(p));
    return a;
}

__device__ __forceinline__ uint32_t swz(uint32_t off) {
    return off ^ (((off >> 7) & 7u) << 4);
}

__device__ __forceinline__ float trunc16f(float x) {
    return __uint_as_float(__float_as_uint(x) & 0xffff0000u);
}

// pack top-16 bits (bf16 truncation) of two floats: low half = x, high = y
__device__ __forceinline__ uint32_t pack_hi2(float x, float y) {
    uint32_t r;
    asm("prmt.b32 %0, %1, %2, 0x7632;"
        : "=r"(r) : "r"(__float_as_uint(x)), "r"(__float_as_uint(y)));
    return r;
}

// rounded bf16x2 pack: low half = lo_elem, high = hi_elem
__device__ __forceinline__ uint32_t cvt2bf(float hi_elem, float lo_elem) {
    uint32_t r;
    asm("cvt.rn.bf16x2.f32 %0, %1, %2;" : "=r"(r) : "f"(hi_elem), "f"(lo_elem));
    return r;
}

// fast 2^x on FMA/ALU pipes (avoids MUFU serialization)
__device__ __forceinline__ float fex2(float x) {
    x = fmaxf(x, -126.0f);
    float n = rintf(x);
    float f = x - n;
    float p = fmaf(0.0096181f, f, 0.0555036f);
    p = fmaf(p, f, 0.2402264f);
    p = fmaf(p, f, 0.6931472f);
    p = fmaf(p, f, 1.0f);
    int e = (int)n;
    return p * __int_as_float((e + 127) << 23);
}

__device__ __forceinline__ void mma_bf16(float c[4],
    uint32_t a0, uint32_t a1, uint32_t a2, uint32_t a3,
    uint32_t b0, uint32_t b1)
{
    asm volatile(
        "mma.sync.aligned.m16n8k16.row.col.f32.bf16.bf16.f32 "
        "{%0,%1,%2,%3}, {%4,%5,%6,%7}, {%8,%9}, {%0,%1,%2,%3};"
        : "+f"(c[0]), "+f"(c[1]), "+f"(c[2]), "+f"(c[3])
        : "r"(a0), "r"(a1), "r"(a2), "r"(a3), "r"(b0), "r"(b1));
}

__device__ __forceinline__ void ldsm_x4(uint32_t r[4], uint32_t addr) {
    asm volatile("ldmatrix.sync.aligned.m8n8.x4.shared.b16 {%0,%1,%2,%3}, [%4];"
                 : "=r"(r[0]), "=r"(r[1]), "=r"(r[2]), "=r"(r[3]) : "r"(addr));
}
__device__ __forceinline__ void ldsm_x4t(uint32_t r[4], uint32_t addr) {
    asm volatile("ldmatrix.sync.aligned.m8n8.x4.trans.shared.b16 {%0,%1,%2,%3}, [%4];"
                 : "=r"(r[0]), "=r"(r[1]), "=r"(r[2]), "=r"(r[3]) : "r"(addr));
}

__device__ __forceinline__ void cpa16(uint32_t dst, const void* src) {
    asm volatile("cp.async.cg.shared.global [%0], [%1], 16;" :: "r"(dst), "l"(src));
}
#define CP_COMMIT()  asm volatile("cp.async.commit_group;" ::: "memory")
#define CP_WAIT0()   asm volatile("cp.async.wait_group 0;" ::: "memory")
#define CP_WAIT1()   asm volatile("cp.async.wait_group 1;" ::: "memory")

// copy one pre-swizzled 16KB tile (global -> smem), 256 threads
__device__ __forceinline__ void cp_tile(uint32_t dsmem, const uint8_t* g, int tid) {
#pragma unroll
    for (int i = 0; i < 4; i++)
        cpa16(dsmem + (tid + 256 * i) * 16, g + (tid + 256 * i) * 16);
}

// Stage a 128x64 fp32 tile into hi/lo bf16 swizzled tiles (smem OR global dst)
__device__ __forceinline__ void stage128(char* dhi, char* dlo,
    const float* __restrict__ g, int ldg, float sc, int tid)
{
#pragma unroll
    for (int i4 = tid; i4 < 2048; i4 += 256) {
        const int r = i4 >> 4, c4 = (i4 & 15) << 2;
        float4 v = *(const float4*)(g + (long long)r * ldg + c4);
        v.x *= sc; v.y *= sc; v.z *= sc; v.w *= sc;
        uint32_t h0 = pack_hi2(v.x, v.y);
        uint32_t h1 = pack_hi2(v.z, v.w);
        uint32_t l0 = cvt2bf(v.y - trunc16f(v.y), v.x - trunc16f(v.x));
        uint32_t l1 = cvt2bf(v.w - trunc16f(v.w), v.z - trunc16f(v.z));
        const uint32_t off = swz((uint32_t)(r * 128 + c4 * 2));
        *(uint2*)(dhi + off) = make_uint2(h0, h1);
        *(uint2*)(dlo + off) = make_uint2(l0, l1);
    }
}

// ===========================================================================
// Stage 0 (prep): Wo fp32 -> bf16 hi/lo swizzled tiles. grid (16 kc, 8 rowblk).
// ===========================================================================
__global__ __launch_bounds__(256) void prep_wo(const float* __restrict__ Wo,
                                               uint8_t* __restrict__ dst)
{
    const int kc = blockIdx.x, by = blockIdx.y;
    uint8_t* hi = dst + (((size_t)by * 16 + kc) * 2 + 0) * TILE_B;
    uint8_t* lo = dst + (((size_t)by * 16 + kc) * 2 + 1) * TILE_B;
    stage128((char*)hi, (char*)lo, Wo + (long long)by * 128 * EMB + kc * 64,
             EMB, 1.0f, threadIdx.x);
}

// ===========================================================================
// Stage 1: K/Q/V shared projections (SIMT fp32). 64x64 tile, K=1024, z=3.
// ===========================================================================
__global__ __launch_bounds__(256) void gemm_qkv2(
    const float* __restrict__ A,
    const float* __restrict__ W0, const float* __restrict__ W1,
    const float* __restrict__ W2, float* __restrict__ C)
{
    __shared__ float AsT[16 * 64];
    __shared__ float BsT[16 * 64];
    const int t = threadIdx.x;
    const int tx = t & 15, ty = t >> 4;
    const int bm = blockIdx.x * 64;
    const int z = blockIdx.z;
    const float* W = (z == 0) ? W0 : ((z == 1) ? W1 : W2);
    float* Cz = C + (long long)z * S_LEN * DH;

    const int lm = t >> 2, k0 = (t & 3) << 2;
    float acc[4][4] = {};

    for (int kc = 0; kc < EMB; kc += 16) {
        float4 av = *(const float4*)(A + (long long)(bm + lm) * EMB + kc + k0);
        float4 bv = *(const float4*)(W + (long long)lm * EMB + kc + k0);
        __syncthreads();
        {
            float a4[4] = {av.x, av.y, av.z, av.w};
            float b4[4] = {bv.x, bv.y, bv.z, bv.w};
#pragma unroll
            for (int i = 0; i < 4; i++) {
                const int sw = (k0 + i) & 12;
                AsT[(k0 + i) * 64 + (lm ^ sw)] = a4[i];
                BsT[(k0 + i) * 64 + (lm ^ sw)] = b4[i];
            }
        }
        __syncthreads();
#pragma unroll
        for (int kk = 0; kk < 16; kk++) {
            const int sw = kk & 12;
            float4 a = *(const float4*)&AsT[kk * 64 + ((4 * ty) ^ sw)];
            float4 b = *(const float4*)&BsT[kk * 64 + ((4 * tx) ^ sw)];
            float ar[4] = {a.x, a.y, a.z, a.w};
            float br[4] = {b.x, b.y, b.z, b.w};
#pragma unroll
            for (int i = 0; i < 4; i++)
#pragma unroll
                for (int j = 0; j < 4; j++)
                    acc[i][j] = fmaf(ar[i], br[j], acc[i][j]);
        }
    }
#pragma unroll
    for (int i = 0; i < 4; i++) {
        const int row = bm + 4 * ty + i;
        *(float4*)&Cz[(long long)row * DH + 4 * tx] =
            make_float4(acc[i][0], acc[i][1], acc[i][2], acc[i][3]);
    }
}

// ===========================================================================
// Stage 2: per-head linears (SIMT fp32) -> bf16 hi/lo swizzled tiles.
// z in [0,48) = tz*16 + head. Q (tz==1) pre-scaled by log2e/sqrt(D).
// ===========================================================================
__global__ __launch_bounds__(256) void gemm_heads(
    const float* __restrict__ X,
    const float* __restrict__ Wk_, const float* __restrict__ bk_,
    const float* __restrict__ Wq_, const float* __restrict__ bq_,
    const float* __restrict__ Wv_, const float* __restrict__ bv_,
    uint8_t* __restrict__ Outbf)
{
    __shared__ float AsT[16 * 64];
    __shared__ float BsT[16 * 64];
    const int t = threadIdx.x;
    const int tx = t & 15, ty = t >> 4;
    const int bm = blockIdx.x * 64;
    const int z = blockIdx.z;
    const int tz = z >> 4, hh = z & 15;

    const float* A = X + (long long)tz * S_LEN * DH;
    const float* W = ((tz == 0) ? Wk_ : ((tz == 1) ? Wq_ : Wv_)) + hh * DH * DH;
    const float* bb = ((tz == 0) ? bk_ : ((tz == 1) ? bq_ : bv_)) + hh * DH;

    const int lm = t >> 2, k0 = (t & 3) << 2;
    float acc[4][4] = {};

    for (int kc = 0; kc < DH; kc += 16) {
        float4 av = *(const float4*)(A + (long long)(bm + lm) * DH + kc + k0);
        float4 bv4 = *(const float4*)(W + (long long)lm * DH + kc + k0);
        __syncthreads();
        {
            float a4[4] = {av.x, av.y, av.z, av.w};
            float b4[4] = {bv4.x, bv4.y, bv4.z, bv4.w};
#pragma unroll
            for (int i = 0; i < 4; i++) {
                const int sw = (k0 + i) & 12;
                AsT[(k0 + i) * 64 + (lm ^ sw)] = a4[i];
                BsT[(k0 + i) * 64 + (lm ^ sw)] = b4[i];
            }
        }
        __syncthreads();
#pragma unroll
        for (int kk = 0; kk < 16; kk++) {
            const int sw = kk & 12;
            float4 a = *(const float4*)&AsT[kk * 64 + ((4 * ty) ^ sw)];
            float4 b = *(const float4*)&BsT[kk * 64 + ((4 * tx) ^ sw)];
            float ar[4] = {a.x, a.y, a.z, a.w};
            float br[4] = {b.x, b.y, b.z, b.w};
#pragma unroll
            for (int i = 0; i < 4; i++)
#pragma unroll
                for (int j = 0; j < 4; j++)
                    acc[i][j] = fmaf(ar[i], br[j], acc[i][j]);
        }
    }

    const float SC = (tz == 1) ? (0.125f * 1.44269504088896340736f) : 1.0f;
    float4 bias4 = *(const float4*)&bb[4 * tx];
#pragma unroll
    for (int i = 0; i < 4; i++) {
        const int row = bm + 4 * ty + i;
        const int rb = row >> 7, rit = row & 127;
        uint8_t* hi = Outbf + ((((size_t)z * 16 + rb) * 2) + 0) * TILE_B;
        uint8_t* lo = Outbf + ((((size_t)z * 16 + rb) * 2) + 1) * TILE_B;
        float v0 = (acc[i][0] + bias4.x) * SC;
        float v1 = (acc[i][1] + bias4.y) * SC;
        float v2 = (acc[i][2] + bias4.z) * SC;
        float v3 = (acc[i][3] + bias4.w) * SC;
        const uint32_t off = swz((uint32_t)(rit * 128 + 4 * tx * 2));
        *(uint2*)(hi + off) = make_uint2(pack_hi2(v0, v1), pack_hi2(v2, v3));
        *(uint2*)(lo + off) = make_uint2(
            cvt2bf(v1 - trunc16f(v1), v0 - trunc16f(v0)),
            cvt2bf(v3 - trunc16f(v3), v2 - trunc16f(v2)));
    }
}

// ===========================================================================
// Stage 3: flash attention on HMMA (bf16x3 split, fp32 accum).
// Pre-converted tiles; cp.async staging with commit-group overlap:
//   V(kb) copy overlaps S-phase; K(kb+1) copy overlaps second PV-phase.
// ===========================================================================
#define ATT_SMEM 65536

__global__ __launch_bounds__(256, 2) void attn_mma(
    const uint8_t* __restrict__ Hbf, uint8_t* __restrict__ catbf)
{
    extern __shared__ char sm[];
    const uint32_t sKHI = smem_u32(sm);
    const uint32_t sKLO = sKHI + TILE_B;
    const uint32_t sVHI = sKLO + TILE_B;
    const uint32_t sVLO = sVHI + TILE_B;

    const int tid = threadIdx.x;
    const int w = tid >> 5, l = tid & 31;
    const int qb = blockIdx.x, h = blockIdx.y;
    const int rl = l & 7, mi = l >> 3;

    // tile base pointers: Hbf[(tz*16+h)*16 + blk][hi/lo]
    const uint8_t* Kt = Hbf + (((size_t)(0 * NH + h) * 16) * 2) * TILE_B;
    const uint8_t* Qt = Hbf + (((size_t)(1 * NH + h) * 16 + qb) * 2) * TILE_B;
    const uint8_t* Vt = Hbf + (((size_t)(2 * NH + h) * 16) * 2) * TILE_B;

    // prologue: K(0) then Q (into V buffers)
    cp_tile(sKHI, Kt + 0 * 2 * TILE_B, tid);
    cp_tile(sKLO, Kt + 0 * 2 * TILE_B + TILE_B, tid);
    CP_COMMIT();
    cp_tile(sVHI, Qt, tid);
    cp_tile(sVLO, Qt + TILE_B, tid);
    CP_COMMIT();
    CP_WAIT0();
    __syncthreads();

    uint32_t aqh[4][4], aql[4][4];
    {
        const int aRow = 16 * w + rl + ((mi & 1) ? 8 : 0);
        const int cAdd = (mi & 2) ? 8 : 0;
#pragma unroll
        for (int s = 0; s < 4; s++) {
            const uint32_t off = swz((uint32_t)(aRow * 128 + (16 * s + cAdd) * 2));
            ldsm_x4(aqh[s], sVHI + off);
            ldsm_x4(aql[s], sVLO + off);
        }
    }
    __syncthreads();

    float o[8][4];
#pragma unroll
    for (int j = 0; j < 8; j++)
#pragma unroll
        for (int k = 0; k < 4; k++) o[j][k] = 0.0f;
    float m0 = -1e30f, m1 = -1e30f, l0 = 0.0f, l1 = 0.0f;

    for (int kb = 0; kb < S_LEN / 128; kb++) {
        // V(kb) copy (overlaps S phase below)
        cp_tile(sVHI, Vt + (size_t)kb * 2 * TILE_B, tid);
        cp_tile(sVLO, Vt + (size_t)kb * 2 * TILE_B + TILE_B, tid);
        CP_COMMIT();
        CP_WAIT1();           // K(kb) complete (V may still be in flight)
        __syncthreads();

#pragma unroll
        for (int hf = 0; hf < 2; hf++) {
            // ---- S = Q @ K^T (16 x 64 per warp), bf16x3
            float s[8][4];
#pragma unroll
            for (int j = 0; j < 8; j++)
#pragma unroll
                for (int k = 0; k < 4; k++) s[j][k] = 0.0f;

#pragma unroll
            for (int jj = 0; jj < 4; jj++) {
                const int nrow = hf * 64 + 16 * jj + rl + ((mi & 2) ? 8 : 0);
#pragma unroll
                for (int ks = 0; ks < 4; ks++) {
                    const int kcol = 16 * ks + ((mi & 1) ? 8 : 0);
                    const uint32_t off = swz((uint32_t)(nrow * 128 + kcol * 2));
                    uint32_t bh[4], bl[4];
                    ldsm_x4(bh, sKHI + off);
                    ldsm_x4(bl, sKLO + off);
                    mma_bf16(s[2 * jj], aqh[ks][0], aqh[ks][1], aqh[ks][2], aqh[ks][3], bh[0], bh[1]);
                    mma_bf16(s[2 * jj], aqh[ks][0], aqh[ks][1], aqh[ks][2], aqh[ks][3], bl[0], bl[1]);
                    mma_bf16(s[2 * jj], aql[ks][0], aql[ks][1], aql[ks][2], aql[ks][3], bh[0], bh[1]);
                    mma_bf16(s[2 * jj + 1], aqh[ks][0], aqh[ks][1], aqh[ks][2], aqh[ks][3], bh[2], bh[3]);
                    mma_bf16(s[2 * jj + 1], aqh[ks][0], aqh[ks][1], aqh[ks][2], aqh[ks][3], bl[2], bl[3]);
                    mma_bf16(s[2 * jj + 1], aql[ks][0], aql[ks][1], aql[ks][2], aql[ks][3], bh[2], bh[3]);
                }
            }

            // ---- online softmax (exp2 domain, FMA-pipe poly)
            float rm0 = -1e30f, rm1 = -1e30f;
#pragma unroll
            for (int j = 0; j < 8; j++) {
                rm0 = fmaxf(rm0, fmaxf(s[j][0], s[j][1]));
                rm1 = fmaxf(rm1, fmaxf(s[j][2], s[j][3]));
            }
            rm0 = fmaxf(rm0, __shfl_xor_sync(0xffffffffu, rm0, 1));
            rm0 = fmaxf(rm0, __shfl_xor_sync(0xffffffffu, rm0, 2));
            rm1 = fmaxf(rm1, __shfl_xor_sync(0xffffffffu, rm1, 1));
            rm1 = fmaxf(rm1, __shfl_xor_sync(0xffffffffu, rm1, 2));
            const float mn0 = fmaxf(m0, rm0), mn1 = fmaxf(m1, rm1);
            const float al0 = fex2(m0 - mn0), al1 = fex2(m1 - mn1);
            m0 = mn0; m1 = mn1;

            float sum0 = 0.0f, sum1 = 0.0f;
#pragma unroll
            for (int j = 0; j < 8; j++) {
                s[j][0] = fex2(s[j][0] - mn0);
                s[j][1] = fex2(s[j][1] - mn0);
                s[j][2] = fex2(s[j][2] - mn1);
                s[j][3] = fex2(s[j][3] - mn1);
                sum0 += s[j][0] + s[j][1];
                sum1 += s[j][2] + s[j][3];
            }
            sum0 += __shfl_xor_sync(0xffffffffu, sum0, 1);
            sum0 += __shfl_xor_sync(0xffffffffu, sum0, 2);
            sum1 += __shfl_xor_sync(0xffffffffu, sum1, 1);
            sum1 += __shfl_xor_sync(0xffffffffu, sum1, 2);
            l0 = l0 * al0 + sum0;
            l1 = l1 * al1 + sum1;
#pragma unroll
            for (int j = 0; j < 8; j++) {
                o[j][0] *= al0; o[j][1] *= al0;
                o[j][2] *= al1; o[j][3] *= al1;
            }

            // ---- pack P fragments (hi trunc + lo residual)
            uint32_t pah[4][4], pal[4][4];
#pragma unroll
            for (int ks = 0; ks < 4; ks++) {
                const int j0 = 2 * ks, j1 = 2 * ks + 1;
                pah[ks][0] = pack_hi2(s[j0][0], s[j0][1]);
                pah[ks][1] = pack_hi2(s[j0][2], s[j0][3]);
                pah[ks][2] = pack_hi2(s[j1][0], s[j1][1]);
                pah[ks][3] = pack_hi2(s[j1][2], s[j1][3]);
                pal[ks][0] = cvt2bf(s[j0][1] - trunc16f(s[j0][1]), s[j0][0] - trunc16f(s[j0][0]));
                pal[ks][1] = cvt2bf(s[j0][3] - trunc16f(s[j0][3]), s[j0][2] - trunc16f(s[j0][2]));
                pal[ks][2] = cvt2bf(s[j1][1] - trunc16f(s[j1][1]), s[j1][0] - trunc16f(s[j1][0]));
                pal[ks][3] = cvt2bf(s[j1][3] - trunc16f(s[j1][3]), s[j1][2] - trunc16f(s[j1][2]));
            }

            if (hf == 0) {
                CP_WAIT0();          // V(kb) landed
                __syncthreads();
            } else {
                __syncthreads();     // all warps done reading K
                if (kb + 1 < S_LEN / 128) {   // K(kb+1) copy overlaps PV(hf=1)
                    cp_tile(sKHI, Kt + (size_t)(kb + 1) * 2 * TILE_B, tid);
                    cp_tile(sKLO, Kt + (size_t)(kb + 1) * 2 * TILE_B + TILE_B, tid);
                    CP_COMMIT();
                }
            }

            // ---- O += P @ V, bf16x3
#pragma unroll
            for (int jj = 0; jj < 4; jj++) {
                const int ncol = 16 * jj + ((mi & 2) ? 8 : 0);
#pragma unroll
                for (int ks = 0; ks < 4; ks++) {
                    const int krow = hf * 64 + 16 * ks + rl + ((mi & 1) ? 8 : 0);
                    const uint32_t off = swz((uint32_t)(krow * 128 + ncol * 2));
                    uint32_t vh[4], vl[4];
                    ldsm_x4t(vh, sVHI + off);
                    ldsm_x4t(vl, sVLO + off);
                    mma_bf16(o[2 * jj], pah[ks][0], pah[ks][1], pah[ks][2], pah[ks][3], vh[0], vh[1]);
                    mma_bf16(o[2 * jj], pah[ks][0], pah[ks][1], pah[ks][2], pah[ks][3], vl[0], vl[1]);
                    mma_bf16(o[2 * jj], pal[ks][0], pal[ks][1], pal[ks][2], pal[ks][3], vh[0], vh[1]);
                    mma_bf16(o[2 * jj + 1], pah[ks][0], pah[ks][1], pah[ks][2], pah[ks][3], vh[2], vh[3]);
                    mma_bf16(o[2 * jj + 1], pah[ks][0], pah[ks][1], pah[ks][2], pah[ks][3], vl[2], vl[3]);
                    mma_bf16(o[2 * jj + 1], pal[ks][0], pal[ks][1], pal[ks][2], pal[ks][3], vh[2], vh[3]);
                }
            }
        }
        __syncthreads();   // V buffer free for next iteration's copy
    }

    // ---- epilogue: normalize, split hi/lo, write pre-swizzled cat tiles
    const float i0 = 1.0f / l0, i1 = 1.0f / l1;
    uint8_t* chi = catbf + (((size_t)qb * NH + h) * 2 + 0) * TILE_B;
    uint8_t* clo = catbf + (((size_t)qb * NH + h) * 2 + 1) * TILE_B;
    const int rit0 = 16 * w + (l >> 2);
#pragma unroll
    for (int j = 0; j < 8; j++) {
        const int col = 8 * j + 2 * (l & 3);
        float v0 = o[j][0] * i0, v1 = o[j][1] * i0;
        float v2 = o[j][2] * i1, v3 = o[j][3] * i1;
        const uint32_t off0 = swz((uint32_t)(rit0 * 128 + col * 2));
        const uint32_t off1 = swz((uint32_t)((rit0 + 8) * 128 + col * 2));
        *(uint32_t*)(chi + off0) = pack_hi2(v0, v1);
        *(uint32_t*)(clo + off0) = cvt2bf(v1 - trunc16f(v1), v0 - trunc16f(v0));
        *(uint32_t*)(chi + off1) = pack_hi2(v2, v3);
        *(uint32_t*)(clo + off1) = cvt2bf(v3 - trunc16f(v3), v2 - trunc16f(v2));
    }
}

// ===========================================================================
// Stage 4: out = cat @ Wo^T + bo + x. Pre-converted operands, cp.async
// double-buffered (128KB smem, 1 CTA/SM). CTA 128x128, 8 warps.
// ===========================================================================
#define GM_SMEM 131072

__global__ __launch_bounds__(256) void gemm_mma(
    const uint8_t* __restrict__ Abf, const uint8_t* __restrict__ Bbf,
    const float* __restrict__ bias, const float* __restrict__ res,
    float* __restrict__ C)
{
    extern __shared__ char sm[];
    const uint32_t base = smem_u32(sm);

    const int tid = threadIdx.x;
    const int w = tid >> 5, l = tid & 31;
    const int rl = l & 7, mi = l >> 3;
    const int wm = w & 1, wn = w >> 1;
    const int bx = blockIdx.x, by = blockIdx.y;
    const int bm = bx * 128, bn = by * 128;

    float c[4][4][4];
#pragma unroll
    for (int a = 0; a < 4; a++)
#pragma unroll
        for (int b = 0; b < 4; b++)
#pragma unroll
            for (int k = 0; k < 4; k++) c[a][b][k] = 0.0f;

    // stage buffers: [2][AH,AL,BH,BL] x 16KB
    auto issue = [&](int k) {
        const uint32_t st = base + (uint32_t)(k & 1) * 65536;
        const uint8_t* At = Abf + (((size_t)bx * 16 + k) * 2) * TILE_B;
        const uint8_t* Bt = Bbf + (((size_t)by * 16 + k) * 2) * TILE_B;
        cp_tile(st,                At,          tid);
        cp_tile(st + TILE_B,       At + TILE_B, tid);
        cp_tile(st + 2 * TILE_B,   Bt,          tid);
        cp_tile(st + 3 * TILE_B,   Bt + TILE_B, tid);
        CP_COMMIT();
    };

    issue(0);
    for (int kc = 0; kc < 16; kc++) {
        if (kc + 1 < 16) issue(kc + 1);
        if (kc + 1 < 16) { CP_WAIT1(); } else { CP_WAIT0(); }
        __syncthreads();

        const uint32_t st = base + (uint32_t)(kc & 1) * 65536;
        const uint32_t sAH = st, sAL = st + TILE_B;
        const uint32_t sBH = st + 2 * TILE_B, sBL = st + 3 * TILE_B;

#pragma unroll
        for (int ks = 0; ks < 4; ks++) {
            uint32_t ah[4][4], al_[4][4];
            const int aRow0 = 64 * wm + rl + ((mi & 1) ? 8 : 0);
            const int aCAdd = (mi & 2) ? 8 : 0;
#pragma unroll
            for (int mt = 0; mt < 4; mt++) {
                const uint32_t off =
                    swz((uint32_t)((aRow0 + 16 * mt) * 128 + (16 * ks + aCAdd) * 2));
                ldsm_x4(ah[mt], sAH + off);
                ldsm_x4(al_[mt], sAL + off);
            }
            uint32_t bhf[4][2], blf[4][2];
            const int bRowAdd = (mi & 2) ? 8 : 0;
            const int bCol = 16 * ks + ((mi & 1) ? 8 : 0);
#pragma unroll
            for (int jj = 0; jj < 2; jj++) {
                const int nrow = 32 * wn + 16 * jj + rl + bRowAdd;
                const uint32_t off = swz((uint32_t)(nrow * 128 + bCol * 2));
                uint32_t t4[4], u4[4];
                ldsm_x4(t4, sBH + off);
                ldsm_x4(u4, sBL + off);
                bhf[2 * jj][0] = t4[0]; bhf[2 * jj][1] = t4[1];
                bhf[2 * jj + 1][0] = t4[2]; bhf[2 * jj + 1][1] = t4[3];
                blf[2 * jj][0] = u4[0]; blf[2 * jj][1] = u4[1];
                blf[2 * jj + 1][0] = u4[2]; blf[2 * jj + 1][1] = u4[3];
            }
#pragma unroll
            for (int mt = 0; mt < 4; mt++)
#pragma unroll
                for (int nt = 0; nt < 4; nt++) {
                    mma_bf16(c[mt][nt], ah[mt][0], ah[mt][1], ah[mt][2], ah[mt][3],
                             bhf[nt][0], bhf[nt][1]);
                    mma_bf16(c[mt][nt], ah[mt][0], ah[mt][1], ah[mt][2], ah[mt][3],
                             blf[nt][0], blf[nt][1]);
                    mma_bf16(c[mt][nt], al_[mt][0], al_[mt][1], al_[mt][2], al_[mt][3],
                             bhf[nt][0], bhf[nt][1]);
                }
        }
        __syncthreads();
    }

    // epilogue: + bias + residual
#pragma unroll
    for (int mt = 0; mt < 4; mt++) {
        const int row0 = bm + 64 * wm + 16 * mt + (l >> 2);
#pragma unroll
        for (int nt = 0; nt < 4; nt++) {
            const int col = bn + 32 * wn + 8 * nt + 2 * (l & 3);
            float2 bb = *(const float2*)&bias[col];
            float2 r0v = *(const float2*)&res[(long long)row0 * EMB + col];
            float2 r1v = *(const float2*)&res[(long long)(row0 + 8) * EMB + col];
            *(float2*)&C[(long long)row0 * EMB + col] =
                make_float2(c[mt][nt][0] + bb.x + r0v.x, c[mt][nt][1] + bb.y + r0v.y);
            *(float2*)&C[(long long)(row0 + 8) * EMB + col] =
                make_float2(c[mt][nt][2] + bb.x + r1v.x, c[mt][nt][3] + bb.y + r1v.y);
        }
    }
}

// ---------------------------------------------------------------------------
__global__ __launch_bounds__(256) void ln_kernel(
    const float* __restrict__ Y, const float* __restrict__ gamma,
    const float* __restrict__ beta, float* __restrict__ out)
{
    __shared__ float red1[8], red2[8];
    __shared__ float tot[2];
    const int row = blockIdx.x;
    const int t = threadIdx.x;

    float4 v = *(const float4*)(Y + (long long)row * EMB + 4 * t);
    float s1 = v.x + v.y + v.z + v.w;
    float s2 = v.x * v.x + v.y * v.y + v.z * v.z + v.w * v.w;
#pragma unroll
    for (int o_ = 16; o_ > 0; o_ >>= 1) {
        s1 += __shfl_xor_sync(0xffffffffu, s1, o_);
        s2 += __shfl_xor_sync(0xffffffffu, s2, o_);
    }
    const int wid = t >> 5, lane = t & 31;
    if (lane == 0) { red1[wid] = s1; red2[wid] = s2; }
    __syncthreads();
    if (t == 0) {
        float a = 0.0f, b = 0.0f;
#pragma unroll
        for (int i = 0; i < 8; i++) { a += red1[i]; b += red2[i]; }
        tot[0] = a; tot[1] = b;
    }
    __syncthreads();
    const float mu   = tot[0] * (1.0f / EMB);
    const float var  = tot[1] * (1.0f / EMB) - mu * mu;
    const float rstd = rsqrtf(var + 1e-5f);

    float4 g  = *(const float4*)&gamma[4 * t];
    float4 bb = *(const float4*)&beta[4 * t];
    float4 o4;
    o4.x = (v.x - mu) * rstd * g.x + bb.x;
    o4.y = (v.y - mu) * rstd * g.y + bb.y;
    o4.z = (v.z - mu) * rstd * g.z + bb.z;
    o4.w = (v.w - mu) * rstd * g.w + bb.w;
    *(float4*)&out[(long long)row * EMB + 4 * t] = o4;
}

// ---------------------------------------------------------------------------
extern "C" void kernel_launch(void* const* d_in, const int* in_sizes, int n_in,
                              void* d_out, int out_size)
{
    const float* x     = (const float*)d_in[0];
    const float* Wk    = (const float*)d_in[1];
    const float* Wq    = (const float*)d_in[2];
    const float* Wv    = (const float*)d_in[3];
    const float* hWk   = (const float*)d_in[4];
    const float* hbk   = (const float*)d_in[5];
    const float* hWv   = (const float*)d_in[6];
    const float* hbv   = (const float*)d_in[7];
    const float* hWq   = (const float*)d_in[8];
    const float* hbq   = (const float*)d_in[9];
    const float* Wo    = (const float*)d_in[10];
    const float* bo    = (const float*)d_in[11];
    const float* gamma = (const float*)d_in[12];
    const float* beta  = (const float*)d_in[13];
    float* out = (float*)d_out;

    float *pKQV, *py;
    uint8_t *pHbf, *pcatbf, *pWobf;
    cudaGetSymbolAddress((void**)&pKQV,   g_KQV);
    cudaGetSymbolAddress((void**)&py,     g_y);
    cudaGetSymbolAddress((void**)&pHbf,   g_Hbf);
    cudaGetSymbolAddress((void**)&pcatbf, g_catbf);
    cudaGetSymbolAddress((void**)&pWobf,  g_Wobf);

    cudaFuncSetAttribute(attn_mma, cudaFuncAttributeMaxDynamicSharedMemorySize, ATT_SMEM);
    cudaFuncSetAttribute(gemm_mma, cudaFuncAttributeMaxDynamicSharedMemorySize, GM_SMEM);

    // 1: K,Q,V = x @ W^T (fp32)
    gemm_qkv2<<<dim3(32, 1, 3), 256>>>(x, Wk, Wq, Wv, pKQV);

    // 2: per-head linears -> bf16 hi/lo tiles (Q pre-scaled)
    gemm_heads<<<dim3(32, 1, 48), 256>>>(pKQV, hWk, hbk, hWq, hbq, hWv, hbv, pHbf);

    // 3: Wo -> bf16 hi/lo tiles
    prep_wo<<<dim3(16, 8), 256>>>(Wo, pWobf);

    // 4: flash attention (HMMA bf16x3) -> cat bf16 tiles   [ncu slot 4]
    attn_mma<<<dim3(16, NH), 256, ATT_SMEM>>>(pHbf, pcatbf);

    // 5: out = cat @ Wo^T + bo + x (HMMA bf16x3)           [ncu slot 5]
    gemm_mma<<<dim3(16, 8), 256, GM_SMEM>>>(pcatbf, pWobf, bo, x, py);

    // 6: LayerNorm
    ln_kernel<<<S_LEN, 256>>>(py, gamma, beta, out);
}

// round 11
// speedup vs baseline: 3.7029x; 1.3508x over previous
#include <cuda_runtime.h>
#include <math.h>
#include <stdint.h>

#define S_LEN 2048
#define EMB   1024
#define DH    64
#define NH    16
#define TILE_B 16384   // one 128x64 bf16 tile, 128B rows, swizzled

// Scratch (device globals; no allocations allowed)
__device__ float   g_KQV[3 * S_LEN * DH];                // K,Q,V fp32
__device__ uint8_t g_xbf[16ull * 16 * 2 * TILE_B];       // x bf16 hi/lo tiles [rb][kc]
__device__ uint8_t g_wbf[3ull * 16 * TILE_B];            // Wk/Wq/Wv tiles [z][kc] (hi8KB+lo8KB)
__device__ uint8_t g_Hbf[3ull * NH * 16 * 2 * TILE_B];   // per-head K/Q (bf16 hi/lo), V (fp16 in hi slot)
__device__ uint8_t g_catbf[16ull * NH * 2 * TILE_B];     // attention out bf16 tiles
__device__ uint8_t g_Wobf[8ull * 16 * 2 * TILE_B];       // Wo bf16 tiles
__device__ float   g_y[S_LEN * EMB];                     // pre-LayerNorm

// ===========================================================================
// Helpers (baseline PTX only — build pipeline rejects sm_103a-specific ops)
// ===========================================================================
__device__ __forceinline__ uint32_t smem_u32(const void* p) {
    uint32_t a;
    asm("{ .reg .u64 t; cvta.to.shared.u64 t, %1; cvt.u32.u64 %0, t; }"
        : "=r"(a) : "l"(p));
    return a;
}

__device__ __forceinline__ uint32_t swz(uint32_t off) {
    return off ^ (((off >> 7) & 7u) << 4);
}

__device__ __forceinline__ float trunc16f(float x) {
    return __uint_as_float(__float_as_uint(x) & 0xffff0000u);
}

// pack top-16 bits (bf16 truncation) of two floats: low half = x, high = y
__device__ __forceinline__ uint32_t pack_hi2(float x, float y) {
    uint32_t r;
    asm("prmt.b32 %0, %1, %2, 0x7632;"
        : "=r"(r) : "r"(__float_as_uint(x)), "r"(__float_as_uint(y)));
    return r;
}

// rounded bf16x2 pack: low half = lo_elem, high half = hi_elem
__device__ __forceinline__ uint32_t cvt2bf(float hi_elem, float lo_elem) {
    uint32_t r;
    asm("cvt.rn.bf16x2.f32 %0, %1, %2;" : "=r"(r) : "f"(hi_elem), "f"(lo_elem));
    return r;
}
// rounded fp16x2 pack: low half = lo_elem, high half = hi_elem
__device__ __forceinline__ uint32_t cvt2f16(float hi_elem, float lo_elem) {
    uint32_t r;
    asm("cvt.rn.f16x2.f32 %0, %1, %2;" : "=r"(r) : "f"(hi_elem), "f"(lo_elem));
    return r;
}

// fast 2^x on FMA/ALU pipes (avoids MUFU serialization)
__device__ __forceinline__ float fex2(float x) {
    x = fmaxf(x, -126.0f);
    float n = rintf(x);
    float f = x - n;
    float p = fmaf(0.0096181f, f, 0.0555036f);
    p = fmaf(p, f, 0.2402264f);
    p = fmaf(p, f, 0.6931472f);
    p = fmaf(p, f, 1.0f);
    int e = (int)n;
    return p * __int_as_float((e + 127) << 23);
}

__device__ __forceinline__ void mma_bf16(float c[4],
    uint32_t a0, uint32_t a1, uint32_t a2, uint32_t a3,
    uint32_t b0, uint32_t b1)
{
    asm volatile(
        "mma.sync.aligned.m16n8k16.row.col.f32.bf16.bf16.f32 "
        "{%0,%1,%2,%3}, {%4,%5,%6,%7}, {%8,%9}, {%0,%1,%2,%3};"
        : "+f"(c[0]), "+f"(c[1]), "+f"(c[2]), "+f"(c[3])
        : "r"(a0), "r"(a1), "r"(a2), "r"(a3), "r"(b0), "r"(b1));
}

__device__ __forceinline__ void mma_f16(float c[4],
    uint32_t a0, uint32_t a1, uint32_t a2, uint32_t a3,
    uint32_t b0, uint32_t b1)
{
    asm volatile(
        "mma.sync.aligned.m16n8k16.row.col.f32.f16.f16.f32 "
        "{%0,%1,%2,%3}, {%4,%5,%6,%7}, {%8,%9}, {%0,%1,%2,%3};"
        : "+f"(c[0]), "+f"(c[1]), "+f"(c[2]), "+f"(c[3])
        : "r"(a0), "r"(a1), "r"(a2), "r"(a3), "r"(b0), "r"(b1));
}

__device__ __forceinline__ void ldsm_x4(uint32_t r[4], uint32_t addr) {
    asm volatile("ldmatrix.sync.aligned.m8n8.x4.shared.b16 {%0,%1,%2,%3}, [%4];"
                 : "=r"(r[0]), "=r"(r[1]), "=r"(r[2]), "=r"(r[3]) : "r"(addr));
}
__device__ __forceinline__ void ldsm_x4t(uint32_t r[4], uint32_t addr) {
    asm volatile("ldmatrix.sync.aligned.m8n8.x4.trans.shared.b16 {%0,%1,%2,%3}, [%4];"
                 : "=r"(r[0]), "=r"(r[1]), "=r"(r[2]), "=r"(r[3]) : "r"(addr));
}

__device__ __forceinline__ void cpa16(uint32_t dst, const void* src) {
    asm volatile("cp.async.cg.shared.global [%0], [%1], 16;" :: "r"(dst), "l"(src));
}
#define CP_COMMIT()  asm volatile("cp.async.commit_group;" ::: "memory")
#define CP_WAIT0()   asm volatile("cp.async.wait_group 0;" ::: "memory")
#define CP_WAIT1()   asm volatile("cp.async.wait_group 1;" ::: "memory")

// copy one pre-swizzled 16KB tile (global -> smem), 256 threads
__device__ __forceinline__ void cp_tile(uint32_t dsmem, const uint8_t* g, int tid) {
#pragma unroll
    for (int i = 0; i < 4; i++)
        cpa16(dsmem + (tid + 256 * i) * 16, g + (tid + 256 * i) * 16);
}

// Stage a 128x64 fp32 tile into hi/lo bf16 swizzled tiles
__device__ __forceinline__ void stage128(char* dhi, char* dlo,
    const float* __restrict__ g, int ldg, float sc, int tid)
{
#pragma unroll
    for (int i4 = tid; i4 < 2048; i4 += 256) {
        const int r = i4 >> 4, c4 = (i4 & 15) << 2;
        float4 v = *(const float4*)(g + (long long)r * ldg + c4);
        v.x *= sc; v.y *= sc; v.z *= sc; v.w *= sc;
        uint32_t h0 = pack_hi2(v.x, v.y);
        uint32_t h1 = pack_hi2(v.z, v.w);
        uint32_t l0 = cvt2bf(v.y - trunc16f(v.y), v.x - trunc16f(v.x));
        uint32_t l1 = cvt2bf(v.w - trunc16f(v.w), v.z - trunc16f(v.z));
        const uint32_t off = swz((uint32_t)(r * 128 + c4 * 2));
        *(uint2*)(dhi + off) = make_uint2(h0, h1);
        *(uint2*)(dlo + off) = make_uint2(l0, l1);
    }
}

// ===========================================================================
// Prep kernels: fp32 -> bf16 hi/lo swizzled tiles
// ===========================================================================
__global__ __launch_bounds__(256) void prep_x(const float* __restrict__ x,
                                              uint8_t* __restrict__ dst)
{
    const int kc = blockIdx.x, rb = blockIdx.y;
    uint8_t* hi = dst + (((size_t)rb * 16 + kc) * 2 + 0) * TILE_B;
    uint8_t* lo = dst + (((size_t)rb * 16 + kc) * 2 + 1) * TILE_B;
    stage128((char*)hi, (char*)lo, x + (long long)rb * 128 * EMB + kc * 64,
             EMB, 1.0f, threadIdx.x);
}

__global__ __launch_bounds__(256) void prep_w(
    const float* __restrict__ W0, const float* __restrict__ W1,
    const float* __restrict__ W2, uint8_t* __restrict__ dst)
{
    const int kc = blockIdx.x, z = blockIdx.y;
    const float* W = (z == 0) ? W0 : ((z == 1) ? W1 : W2);
    uint8_t* hi = dst + ((size_t)z * 16 + kc) * TILE_B;
    uint8_t* lo = hi + 8192;
    const int tid = threadIdx.x;
#pragma unroll
    for (int i4 = tid; i4 < 64 * 16; i4 += 256) {
        const int r = i4 >> 4, c4 = (i4 & 15) << 2;
        float4 v = *(const float4*)(W + (long long)r * EMB + kc * 64 + c4);
        const uint32_t off = swz((uint32_t)(r * 128 + c4 * 2));
        *(uint2*)(hi + off) = make_uint2(pack_hi2(v.x, v.y), pack_hi2(v.z, v.w));
        *(uint2*)(lo + off) = make_uint2(
            cvt2bf(v.y - trunc16f(v.y), v.x - trunc16f(v.x)),
            cvt2bf(v.w - trunc16f(v.w), v.z - trunc16f(v.z)));
    }
}

__global__ __launch_bounds__(256) void prep_wo(const float* __restrict__ Wo,
                                               uint8_t* __restrict__ dst)
{
    const int kc = blockIdx.x, by = blockIdx.y;
    uint8_t* hi = dst + (((size_t)by * 16 + kc) * 2 + 0) * TILE_B;
    uint8_t* lo = dst + (((size_t)by * 16 + kc) * 2 + 1) * TILE_B;
    stage128((char*)hi, (char*)lo, Wo + (long long)by * 128 * EMB + kc * 64,
             EMB, 1.0f, threadIdx.x);
}

// ===========================================================================
// Stage 1: K/Q/V = x @ W^T, HMMA bf16x3. grid (16 rowblk, 3 z), 256 thr.
// smem: double-buffered [AH 16K | AL 16K | B 16K(hi8+lo8)] = 96KB.
// Warp w computes rows 16w..16w+15 x all 64 cols (attn S-phase mapping).
// ===========================================================================
#define QKV_SMEM 98304

__global__ __launch_bounds__(256) void gemm_qkv_hmma(
    const uint8_t* __restrict__ xbf, const uint8_t* __restrict__ wbf,
    float* __restrict__ C)
{
    extern __shared__ char sm[];
    const uint32_t base = smem_u32(sm);
    const int tid = threadIdx.x;
    const int w = tid >> 5, l = tid & 31;
    const int rl = l & 7, mi = l >> 3;
    const int rb = blockIdx.x, z = blockIdx.y;

    float s[8][4];
#pragma unroll
    for (int j = 0; j < 8; j++)
#pragma unroll
        for (int k = 0; k < 4; k++) s[j][k] = 0.0f;

    auto issue = [&](int kc) {
        const uint32_t st = base + (uint32_t)(kc & 1) * 49152;
        const uint8_t* At = xbf + (((size_t)rb * 16 + kc) * 2) * TILE_B;
        const uint8_t* Bt = wbf + ((size_t)z * 16 + kc) * TILE_B;
        cp_tile(st, At, tid);
        cp_tile(st + TILE_B, At + TILE_B, tid);
        cp_tile(st + 2 * TILE_B, Bt, tid);
        CP_COMMIT();
    };

    issue(0);
    for (int kc = 0; kc < 16; kc++) {
        if (kc + 1 < 16) { issue(kc + 1); CP_WAIT1(); } else { CP_WAIT0(); }
        __syncthreads();
        const uint32_t st = base + (uint32_t)(kc & 1) * 49152;
        const uint32_t sAH = st, sAL = st + TILE_B;
        const uint32_t sBH = st + 2 * TILE_B, sBL = st + 2 * TILE_B + 8192;

        uint32_t ah[4][4], al_[4][4];
        const int aRow = 16 * w + rl + ((mi & 1) ? 8 : 0);
        const int cAdd = (mi & 2) ? 8 : 0;
#pragma unroll
        for (int ks = 0; ks < 4; ks++) {
            const uint32_t off = swz((uint32_t)(aRow * 128 + (16 * ks + cAdd) * 2));
            ldsm_x4(ah[ks], sAH + off);
            ldsm_x4(al_[ks], sAL + off);
        }
#pragma unroll
        for (int jj = 0; jj < 4; jj++) {
            const int nrow = 16 * jj + rl + ((mi & 2) ? 8 : 0);
#pragma unroll
            for (int ks = 0; ks < 4; ks++) {
                const int kcol = 16 * ks + ((mi & 1) ? 8 : 0);
                const uint32_t off = swz((uint32_t)(nrow * 128 + kcol * 2));
                uint32_t bh[4], bl[4];
                ldsm_x4(bh, sBH + off);
                ldsm_x4(bl, sBL + off);
                mma_bf16(s[2 * jj], ah[ks][0], ah[ks][1], ah[ks][2], ah[ks][3], bh[0], bh[1]);
                mma_bf16(s[2 * jj], ah[ks][0], ah[ks][1], ah[ks][2], ah[ks][3], bl[0], bl[1]);
                mma_bf16(s[2 * jj], al_[ks][0], al_[ks][1], al_[ks][2], al_[ks][3], bh[0], bh[1]);
                mma_bf16(s[2 * jj + 1], ah[ks][0], ah[ks][1], ah[ks][2], ah[ks][3], bh[2], bh[3]);
                mma_bf16(s[2 * jj + 1], ah[ks][0], ah[ks][1], ah[ks][2], ah[ks][3], bl[2], bl[3]);
                mma_bf16(s[2 * jj + 1], al_[ks][0], al_[ks][1], al_[ks][2], al_[ks][3], bh[2], bh[3]);
            }
        }
        __syncthreads();
    }

    float* Cz = C + (size_t)z * S_LEN * DH;
    const int rit0 = rb * 128 + 16 * w + (l >> 2);
#pragma unroll
    for (int j = 0; j < 8; j++) {
        const int col = 8 * j + 2 * (l & 3);
        *(float2*)&Cz[(long long)rit0 * DH + col] = make_float2(s[j][0], s[j][1]);
        *(float2*)&Cz[(long long)(rit0 + 8) * DH + col] = make_float2(s[j][2], s[j][3]);
    }
}

// ===========================================================================
// Stage 2: per-head linears (SIMT fp32) -> tiles.
// K/Q (tz 0/1): bf16 hi/lo; V (tz 2): fp16 single (hi slot). Q pre-scaled.
// ===========================================================================
__global__ __launch_bounds__(256) void gemm_heads(
    const float* __restrict__ X,
    const float* __restrict__ Wk_, const float* __restrict__ bk_,
    const float* __restrict__ Wq_, const float* __restrict__ bq_,
    const float* __restrict__ Wv_, const float* __restrict__ bv_,
    uint8_t* __restrict__ Outbf)
{
    __shared__ float AsT[16 * 64];
    __shared__ float BsT[16 * 64];
    const int t = threadIdx.x;
    const int tx = t & 15, ty = t >> 4;
    const int bm = blockIdx.x * 64;
    const int z = blockIdx.z;
    const int tz = z >> 4, hh = z & 15;

    const float* A = X + (long long)tz * S_LEN * DH;
    const float* W = ((tz == 0) ? Wk_ : ((tz == 1) ? Wq_ : Wv_)) + hh * DH * DH;
    const float* bb = ((tz == 0) ? bk_ : ((tz == 1) ? bq_ : bv_)) + hh * DH;

    const int lm = t >> 2, k0 = (t & 3) << 2;
    float acc[4][4] = {};

    for (int kc = 0; kc < DH; kc += 16) {
        float4 av = *(const float4*)(A + (long long)(bm + lm) * DH + kc + k0);
        float4 bv4 = *(const float4*)(W + (long long)lm * DH + kc + k0);
        __syncthreads();
        {
            float a4[4] = {av.x, av.y, av.z, av.w};
            float b4[4] = {bv4.x, bv4.y, bv4.z, bv4.w};
#pragma unroll
            for (int i = 0; i < 4; i++) {
                const int sw = (k0 + i) & 12;
                AsT[(k0 + i) * 64 + (lm ^ sw)] = a4[i];
                BsT[(k0 + i) * 64 + (lm ^ sw)] = b4[i];
            }
        }
        __syncthreads();
#pragma unroll
        for (int kk = 0; kk < 16; kk++) {
            const int sw = kk & 12;
            float4 a = *(const float4*)&AsT[kk * 64 + ((4 * ty) ^ sw)];
            float4 b = *(const float4*)&BsT[kk * 64 + ((4 * tx) ^ sw)];
            float ar[4] = {a.x, a.y, a.z, a.w};
            float br[4] = {b.x, b.y, b.z, b.w};
#pragma unroll
            for (int i = 0; i < 4; i++)
#pragma unroll
                for (int j = 0; j < 4; j++)
                    acc[i][j] = fmaf(ar[i], br[j], acc[i][j]);
        }
    }

    const float SC = (tz == 1) ? (0.125f * 1.44269504088896340736f) : 1.0f;
    float4 bias4 = *(const float4*)&bb[4 * tx];
#pragma unroll
    for (int i = 0; i < 4; i++) {
        const int row = bm + 4 * ty + i;
        const int rb = row >> 7, rit = row & 127;
        uint8_t* hi = Outbf + ((((size_t)z * 16 + rb) * 2) + 0) * TILE_B;
        uint8_t* lo = Outbf + ((((size_t)z * 16 + rb) * 2) + 1) * TILE_B;
        float v0 = (acc[i][0] + bias4.x) * SC;
        float v1 = (acc[i][1] + bias4.y) * SC;
        float v2 = (acc[i][2] + bias4.z) * SC;
        float v3 = (acc[i][3] + bias4.w) * SC;
        const uint32_t off = swz((uint32_t)(rit * 128 + 4 * tx * 2));
        if (tz == 2) {
            // V: fp16 single precision tile (hi slot only)
            *(uint2*)(hi + off) = make_uint2(cvt2f16(v1, v0), cvt2f16(v3, v2));
        } else {
            *(uint2*)(hi + off) = make_uint2(pack_hi2(v0, v1), pack_hi2(v2, v3));
            *(uint2*)(lo + off) = make_uint2(
                cvt2bf(v1 - trunc16f(v1), v0 - trunc16f(v0)),
                cvt2bf(v3 - trunc16f(v3), v2 - trunc16f(v2)));
        }
    }
}

// ===========================================================================
// Stage 3: flash attention. QK^T: HMMA bf16x3; P.V: HMMA fp16x1.
// Smem 48KB: K hi/lo (32KB) + V fp16 (16KB). cp.async overlap as before.
// ===========================================================================
#define ATT_SMEM 49152

__global__ __launch_bounds__(256, 2) void attn_mma(
    const uint8_t* __restrict__ Hbf, uint8_t* __restrict__ catbf)
{
    extern __shared__ char sm[];
    const uint32_t sKHI = smem_u32(sm);
    const uint32_t sKLO = sKHI + TILE_B;
    const uint32_t sVF  = sKLO + TILE_B;

    const int tid = threadIdx.x;
    const int w = tid >> 5, l = tid & 31;
    const int qb = blockIdx.x, h = blockIdx.y;
    const int rl = l & 7, mi = l >> 3;

    const uint8_t* Kt = Hbf + (((size_t)(0 * NH + h) * 16) * 2) * TILE_B;
    const uint8_t* Qt = Hbf + (((size_t)(1 * NH + h) * 16 + qb) * 2) * TILE_B;
    const uint8_t* Vt = Hbf + (((size_t)(2 * NH + h) * 16) * 2) * TILE_B;  // fp16, hi slots

    // prologue: Q into K buffers, grab fragments, then start K(0)
    cp_tile(sKHI, Qt, tid);
    cp_tile(sKLO, Qt + TILE_B, tid);
    CP_COMMIT();
    CP_WAIT0();
    __syncthreads();

    uint32_t aqh[4][4], aql[4][4];
    {
        const int aRow = 16 * w + rl + ((mi & 1) ? 8 : 0);
        const int cAdd = (mi & 2) ? 8 : 0;
#pragma unroll
        for (int s = 0; s < 4; s++) {
            const uint32_t off = swz((uint32_t)(aRow * 128 + (16 * s + cAdd) * 2));
            ldsm_x4(aqh[s], sKHI + off);
            ldsm_x4(aql[s], sKLO + off);
        }
    }
    __syncthreads();
    cp_tile(sKHI, Kt, tid);
    cp_tile(sKLO, Kt + TILE_B, tid);
    CP_COMMIT();

    float o[8][4];
#pragma unroll
    for (int j = 0; j < 8; j++)
#pragma unroll
        for (int k = 0; k < 4; k++) o[j][k] = 0.0f;
    float m0 = -1e30f, m1 = -1e30f, l0 = 0.0f, l1 = 0.0f;

    for (int kb = 0; kb < S_LEN / 128; kb++) {
        // V(kb) copy (fp16 single tile) — overlaps S phase
        cp_tile(sVF, Vt + (size_t)kb * 2 * TILE_B, tid);
        CP_COMMIT();
        CP_WAIT1();           // K(kb) complete
        __syncthreads();

#pragma unroll
        for (int hf = 0; hf < 2; hf++) {
            // ---- S = Q @ K^T (16 x 64 per warp), bf16x3
            float s[8][4];
#pragma unroll
            for (int j = 0; j < 8; j++)
#pragma unroll
                for (int k = 0; k < 4; k++) s[j][k] = 0.0f;

#pragma unroll
            for (int jj = 0; jj < 4; jj++) {
                const int nrow = hf * 64 + 16 * jj + rl + ((mi & 2) ? 8 : 0);
#pragma unroll
                for (int ks = 0; ks < 4; ks++) {
                    const int kcol = 16 * ks + ((mi & 1) ? 8 : 0);
                    const uint32_t off = swz((uint32_t)(nrow * 128 + kcol * 2));
                    uint32_t bh[4], bl[4];
                    ldsm_x4(bh, sKHI + off);
                    ldsm_x4(bl, sKLO + off);
                    mma_bf16(s[2 * jj], aqh[ks][0], aqh[ks][1], aqh[ks][2], aqh[ks][3], bh[0], bh[1]);
                    mma_bf16(s[2 * jj], aqh[ks][0], aqh[ks][1], aqh[ks][2], aqh[ks][3], bl[0], bl[1]);
                    mma_bf16(s[2 * jj], aql[ks][0], aql[ks][1], aql[ks][2], aql[ks][3], bh[0], bh[1]);
                    mma_bf16(s[2 * jj + 1], aqh[ks][0], aqh[ks][1], aqh[ks][2], aqh[ks][3], bh[2], bh[3]);
                    mma_bf16(s[2 * jj + 1], aqh[ks][0], aqh[ks][1], aqh[ks][2], aqh[ks][3], bl[2], bl[3]);
                    mma_bf16(s[2 * jj + 1], aql[ks][0], aql[ks][1], aql[ks][2], aql[ks][3], bh[2], bh[3]);
                }
            }

            // ---- online softmax (exp2 domain, FMA-pipe poly)
            float rm0 = -1e30f, rm1 = -1e30f;
#pragma unroll
            for (int j = 0; j < 8; j++) {
                rm0 = fmaxf(rm0, fmaxf(s[j][0], s[j][1]));
                rm1 = fmaxf(rm1, fmaxf(s[j][2], s[j][3]));
            }
            rm0 = fmaxf(rm0, __shfl_xor_sync(0xffffffffu, rm0, 1));
            rm0 = fmaxf(rm0, __shfl_xor_sync(0xffffffffu, rm0, 2));
            rm1 = fmaxf(rm1, __shfl_xor_sync(0xffffffffu, rm1, 1));
            rm1 = fmaxf(rm1, __shfl_xor_sync(0xffffffffu, rm1, 2));
            const float mn0 = fmaxf(m0, rm0), mn1 = fmaxf(m1, rm1);
            const float al0 = fex2(m0 - mn0), al1 = fex2(m1 - mn1);
            m0 = mn0; m1 = mn1;

            float sum0 = 0.0f, sum1 = 0.0f;
#pragma unroll
            for (int j = 0; j < 8; j++) {
                s[j][0] = fex2(s[j][0] - mn0);
                s[j][1] = fex2(s[j][1] - mn0);
                s[j][2] = fex2(s[j][2] - mn1);
                s[j][3] = fex2(s[j][3] - mn1);
                sum0 += s[j][0] + s[j][1];
                sum1 += s[j][2] + s[j][3];
            }
            sum0 += __shfl_xor_sync(0xffffffffu, sum0, 1);
            sum0 += __shfl_xor_sync(0xffffffffu, sum0, 2);
            sum1 += __shfl_xor_sync(0xffffffffu, sum1, 1);
            sum1 += __shfl_xor_sync(0xffffffffu, sum1, 2);
            l0 = l0 * al0 + sum0;
            l1 = l1 * al1 + sum1;
#pragma unroll
            for (int j = 0; j < 8; j++) {
                o[j][0] *= al0; o[j][1] *= al0;
                o[j][2] *= al1; o[j][3] *= al1;
            }

            // ---- pack P fragments (fp16)
            uint32_t paf[4][4];
#pragma unroll
            for (int ks = 0; ks < 4; ks++) {
                const int j0 = 2 * ks, j1 = 2 * ks + 1;
                paf[ks][0] = cvt2f16(s[j0][1], s[j0][0]);
                paf[ks][1] = cvt2f16(s[j0][3], s[j0][2]);
                paf[ks][2] = cvt2f16(s[j1][1], s[j1][0]);
                paf[ks][3] = cvt2f16(s[j1][3], s[j1][2]);
            }

            if (hf == 0) {
                CP_WAIT0();          // V(kb) landed
                __syncthreads();
            } else {
                __syncthreads();     // all warps done reading K
                if (kb + 1 < S_LEN / 128) {   // K(kb+1) overlaps PV(hf=1)
                    cp_tile(sKHI, Kt + (size_t)(kb + 1) * 2 * TILE_B, tid);
                    cp_tile(sKLO, Kt + (size_t)(kb + 1) * 2 * TILE_B + TILE_B, tid);
                    CP_COMMIT();
                }
            }

            // ---- O += P @ V, fp16 x1
#pragma unroll
            for (int jj = 0; jj < 4; jj++) {
                const int ncol = 16 * jj + ((mi & 2) ? 8 : 0);
#pragma unroll
                for (int ks = 0; ks < 4; ks++) {
                    const int krow = hf * 64 + 16 * ks + rl + ((mi & 1) ? 8 : 0);
                    const uint32_t off = swz((uint32_t)(krow * 128 + ncol * 2));
                    uint32_t vf[4];
                    ldsm_x4t(vf, sVF + off);
                    mma_f16(o[2 * jj], paf[ks][0], paf[ks][1], paf[ks][2], paf[ks][3], vf[0], vf[1]);
                    mma_f16(o[2 * jj + 1], paf[ks][0], paf[ks][1], paf[ks][2], paf[ks][3], vf[2], vf[3]);
                }
            }
        }
        __syncthreads();   // V buffer free for next iteration's copy
    }

    // ---- epilogue: normalize, split hi/lo, write pre-swizzled cat tiles
    const float i0 = 1.0f / l0, i1 = 1.0f / l1;
    uint8_t* chi = catbf + (((size_t)qb * NH + h) * 2 + 0) * TILE_B;
    uint8_t* clo = catbf + (((size_t)qb * NH + h) * 2 + 1) * TILE_B;
    const int rit0 = 16 * w + (l >> 2);
#pragma unroll
    for (int j = 0; j < 8; j++) {
        const int col = 8 * j + 2 * (l & 3);
        float v0 = o[j][0] * i0, v1 = o[j][1] * i0;
        float v2 = o[j][2] * i1, v3 = o[j][3] * i1;
        const uint32_t off0 = swz((uint32_t)(rit0 * 128 + col * 2));
        const uint32_t off1 = swz((uint32_t)((rit0 + 8) * 128 + col * 2));
        *(uint32_t*)(chi + off0) = pack_hi2(v0, v1);
        *(uint32_t*)(clo + off0) = cvt2bf(v1 - trunc16f(v1), v0 - trunc16f(v0));
        *(uint32_t*)(chi + off1) = pack_hi2(v2, v3);
        *(uint32_t*)(clo + off1) = cvt2bf(v3 - trunc16f(v3), v2 - trunc16f(v2));
    }
}

// ===========================================================================
// Stage 4: out = cat @ Wo^T + bo + x. bf16x3 HMMA, cp.async double-buffered.
// ===========================================================================
#define GM_SMEM 131072

__global__ __launch_bounds__(256) void gemm_mma(
    const uint8_t* __restrict__ Abf, const uint8_t* __restrict__ Bbf,
    const float* __restrict__ bias, const float* __restrict__ res,
    float* __restrict__ C)
{
    extern __shared__ char sm[];
    const uint32_t base = smem_u32(sm);

    const int tid = threadIdx.x;
    const int w = tid >> 5, l = tid & 31;
    const int rl = l & 7, mi = l >> 3;
    const int wm = w & 1, wn = w >> 1;
    const int bx = blockIdx.x, by = blockIdx.y;
    const int bm = bx * 128, bn = by * 128;

    float c[4][4][4];
#pragma unroll
    for (int a = 0; a < 4; a++)
#pragma unroll
        for (int b = 0; b < 4; b++)
#pragma unroll
            for (int k = 0; k < 4; k++) c[a][b][k] = 0.0f;

    auto issue = [&](int k) {
        const uint32_t st = base + (uint32_t)(k & 1) * 65536;
        const uint8_t* At = Abf + (((size_t)bx * 16 + k) * 2) * TILE_B;
        const uint8_t* Bt = Bbf + (((size_t)by * 16 + k) * 2) * TILE_B;
        cp_tile(st,                At,          tid);
        cp_tile(st + TILE_B,       At + TILE_B, tid);
        cp_tile(st + 2 * TILE_B,   Bt,          tid);
        cp_tile(st + 3 * TILE_B,   Bt + TILE_B, tid);
        CP_COMMIT();
    };

    issue(0);
    for (int kc = 0; kc < 16; kc++) {
        if (kc + 1 < 16) { issue(kc + 1); CP_WAIT1(); } else { CP_WAIT0(); }
        __syncthreads();

        const uint32_t st = base + (uint32_t)(kc & 1) * 65536;
        const uint32_t sAH = st, sAL = st + TILE_B;
        const uint32_t sBH = st + 2 * TILE_B, sBL = st + 3 * TILE_B;

#pragma unroll
        for (int ks = 0; ks < 4; ks++) {
            uint32_t ah[4][4], al_[4][4];
            const int aRow0 = 64 * wm + rl + ((mi & 1) ? 8 : 0);
            const int aCAdd = (mi & 2) ? 8 : 0;
#pragma unroll
            for (int mt = 0; mt < 4; mt++) {
                const uint32_t off =
                    swz((uint32_t)((aRow0 + 16 * mt) * 128 + (16 * ks + aCAdd) * 2));
                ldsm_x4(ah[mt], sAH + off);
                ldsm_x4(al_[mt], sAL + off);
            }
            uint32_t bhf[4][2], blf[4][2];
            const int bRowAdd = (mi & 2) ? 8 : 0;
            const int bCol = 16 * ks + ((mi & 1) ? 8 : 0);
#pragma unroll
            for (int jj = 0; jj < 2; jj++) {
                const int nrow = 32 * wn + 16 * jj + rl + bRowAdd;
                const uint32_t off = swz((uint32_t)(nrow * 128 + bCol * 2));
                uint32_t t4[4], u4[4];
                ldsm_x4(t4, sBH + off);
                ldsm_x4(u4, sBL + off);
                bhf[2 * jj][0] = t4[0]; bhf[2 * jj][1] = t4[1];
                bhf[2 * jj + 1][0] = t4[2]; bhf[2 * jj + 1][1] = t4[3];
                blf[2 * jj][0] = u4[0]; blf[2 * jj][1] = u4[1];
                blf[2 * jj + 1][0] = u4[2]; blf[2 * jj + 1][1] = u4[3];
            }
#pragma unroll
            for (int mt = 0; mt < 4; mt++)
#pragma unroll
                for (int nt = 0; nt < 4; nt++) {
                    mma_bf16(c[mt][nt], ah[mt][0], ah[mt][1], ah[mt][2], ah[mt][3],
                             bhf[nt][0], bhf[nt][1]);
                    mma_bf16(c[mt][nt], ah[mt][0], ah[mt][1], ah[mt][2], ah[mt][3],
                             blf[nt][0], blf[nt][1]);
                    mma_bf16(c[mt][nt], al_[mt][0], al_[mt][1], al_[mt][2], al_[mt][3],
                             bhf[nt][0], bhf[nt][1]);
                }
        }
        __syncthreads();
    }

#pragma unroll
    for (int mt = 0; mt < 4; mt++) {
        const int row0 = bm + 64 * wm + 16 * mt + (l >> 2);
#pragma unroll
        for (int nt = 0; nt < 4; nt++) {
            const int col = bn + 32 * wn + 8 * nt + 2 * (l & 3);
            float2 bb = *(const float2*)&bias[col];
            float2 r0v = *(const float2*)&res[(long long)row0 * EMB + col];
            float2 r1v = *(const float2*)&res[(long long)(row0 + 8) * EMB + col];
            *(float2*)&C[(long long)row0 * EMB + col] =
                make_float2(c[mt][nt][0] + bb.x + r0v.x, c[mt][nt][1] + bb.y + r0v.y);
            *(float2*)&C[(long long)(row0 + 8) * EMB + col] =
                make_float2(c[mt][nt][2] + bb.x + r1v.x, c[mt][nt][3] + bb.y + r1v.y);
        }
    }
}

// ---------------------------------------------------------------------------
__global__ __launch_bounds__(256) void ln_kernel(
    const float* __restrict__ Y, const float* __restrict__ gamma,
    const float* __restrict__ beta, float* __restrict__ out)
{
    __shared__ float red1[8], red2[8];
    __shared__ float tot[2];
    const int row = blockIdx.x;
    const int t = threadIdx.x;

    float4 v = *(const float4*)(Y + (long long)row * EMB + 4 * t);
    float s1 = v.x + v.y + v.z + v.w;
    float s2 = v.x * v.x + v.y * v.y + v.z * v.z + v.w * v.w;
#pragma unroll
    for (int o_ = 16; o_ > 0; o_ >>= 1) {
        s1 += __shfl_xor_sync(0xffffffffu, s1, o_);
        s2 += __shfl_xor_sync(0xffffffffu, s2, o_);
    }
    const int wid = t >> 5, lane = t & 31;
    if (lane == 0) { red1[wid] = s1; red2[wid] = s2; }
    __syncthreads();
    if (t == 0) {
        float a = 0.0f, b = 0.0f;
#pragma unroll
        for (int i = 0; i < 8; i++) { a += red1[i]; b += red2[i]; }
        tot[0] = a; tot[1] = b;
    }
    __syncthreads();
    const float mu   = tot[0] * (1.0f / EMB);
    const float var  = tot[1] * (1.0f / EMB) - mu * mu;
    const float rstd = rsqrtf(var + 1e-5f);

    float4 g  = *(const float4*)&gamma[4 * t];
    float4 bb = *(const float4*)&beta[4 * t];
    float4 o4;
    o4.x = (v.x - mu) * rstd * g.x + bb.x;
    o4.y = (v.y - mu) * rstd * g.y + bb.y;
    o4.z = (v.z - mu) * rstd * g.z + bb.z;
    o4.w = (v.w - mu) * rstd * g.w + bb.w;
    *(float4*)&out[(long long)row * EMB + 4 * t] = o4;
}

// ---------------------------------------------------------------------------
extern "C" void kernel_launch(void* const* d_in, const int* in_sizes, int n_in,
                              void* d_out, int out_size)
{
    const float* x     = (const float*)d_in[0];
    const float* Wk    = (const float*)d_in[1];
    const float* Wq    = (const float*)d_in[2];
    const float* Wv    = (const float*)d_in[3];
    const float* hWk   = (const float*)d_in[4];
    const float* hbk   = (const float*)d_in[5];
    const float* hWv   = (const float*)d_in[6];
    const float* hbv   = (const float*)d_in[7];
    const float* hWq   = (const float*)d_in[8];
    const float* hbq   = (const float*)d_in[9];
    const float* Wo    = (const float*)d_in[10];
    const float* bo    = (const float*)d_in[11];
    const float* gamma = (const float*)d_in[12];
    const float* beta  = (const float*)d_in[13];
    float* out = (float*)d_out;

    float *pKQV, *py;
    uint8_t *pxbf, *pwbf, *pHbf, *pcatbf, *pWobf;
    cudaGetSymbolAddress((void**)&pKQV,   g_KQV);
    cudaGetSymbolAddress((void**)&py,     g_y);
    cudaGetSymbolAddress((void**)&pxbf,   g_xbf);
    cudaGetSymbolAddress((void**)&pwbf,   g_wbf);
    cudaGetSymbolAddress((void**)&pHbf,   g_Hbf);
    cudaGetSymbolAddress((void**)&pcatbf, g_catbf);
    cudaGetSymbolAddress((void**)&pWobf,  g_Wobf);

    cudaFuncSetAttribute(gemm_qkv_hmma, cudaFuncAttributeMaxDynamicSharedMemorySize, QKV_SMEM);
    cudaFuncSetAttribute(attn_mma, cudaFuncAttributeMaxDynamicSharedMemorySize, ATT_SMEM);
    cudaFuncSetAttribute(gemm_mma, cudaFuncAttributeMaxDynamicSharedMemorySize, GM_SMEM);

    // prep: x, Wk/Wq/Wv, Wo -> bf16 hi/lo tiles
    prep_x<<<dim3(16, 16), 256>>>(x, pxbf);
    prep_w<<<dim3(16, 3), 256>>>(Wk, Wq, Wv, pwbf);
    prep_wo<<<dim3(16, 8), 256>>>(Wo, pWobf);

    // 1: K,Q,V = x @ W^T (HMMA bf16x3)
    gemm_qkv_hmma<<<dim3(16, 3), 256, QKV_SMEM>>>(pxbf, pwbf, pKQV);

    // 2: per-head linears -> K/Q bf16 hi/lo, V fp16 (Q pre-scaled)
    gemm_heads<<<dim3(32, 1, 48), 256>>>(pKQV, hWk, hbk, hWq, hbq, hWv, hbv, pHbf);

    // 3: flash attention (QK bf16x3, PV fp16) -> cat bf16 tiles
    attn_mma<<<dim3(16, NH), 256, ATT_SMEM>>>(pHbf, pcatbf);

    // 4: out = cat @ Wo^T + bo + x (HMMA bf16x3)
    gemm_mma<<<dim3(16, 8), 256, GM_SMEM>>>(pcatbf, pWobf, bo, x, py);

    // 5: LayerNorm
    ln_kernel<<<S_LEN, 256>>>(py, gamma, beta, out);
}

// round 12
// speedup vs baseline: 3.8865x; 1.0496x over previous
#include <cuda_runtime.h>
#include <cuda_bf16.h>
#include <math.h>
#include <stdint.h>

#define S_LEN 2048
#define EMB   1024
#define DH    64
#define NH    16
#define TILE_B 16384   // one 128x64 bf16 tile, 128B rows, swizzled

// Scratch (device globals; no allocations allowed)
__device__ float   g_KQV[3 * S_LEN * DH];                // K,Q,V fp32 partial (K-split 0)
__device__ float   g_KQV2[3 * S_LEN * DH];               // K-split 1 partial
__device__ uint8_t g_xbf[16ull * 16 * 2 * TILE_B];       // x bf16 hi/lo tiles [rb][kc]
__device__ uint8_t g_wbf[3ull * 16 * TILE_B];            // Wk/Wq/Wv tiles [z][kc] (hi8KB+lo8KB)
__device__ uint8_t g_Hbf[3ull * NH * 16 * 2 * TILE_B];   // per-head K/Q (bf16 hi/lo), V (fp16 in hi slot)
__device__ uint8_t g_catbf[16ull * NH * 2 * TILE_B];     // attention out bf16 tiles
__device__ uint8_t g_Wobf[8ull * 16 * 2 * TILE_B];       // Wo bf16 tiles [rowblk128][kc]
__device__ float   g_y[S_LEN * EMB];                     // pre-LayerNorm

// ===========================================================================
// Helpers (baseline PTX only — build pipeline rejects sm_103a-specific ops)
// ===========================================================================
__device__ __forceinline__ uint32_t smem_u32(const void* p) {
    uint32_t a;
    asm("{ .reg .u64 t; cvta.to.shared.u64 t, %1; cvt.u32.u64 %0, t; }"
        : "=r"(a) : "l"(p));
    return a;
}

__device__ __forceinline__ uint32_t swz(uint32_t off) {
    return off ^ (((off >> 7) & 7u) << 4);
}

__device__ __forceinline__ float trunc16f(float x) {
    return __uint_as_float(__float_as_uint(x) & 0xffff0000u);
}

// pack top-16 bits (bf16 truncation) of two floats: low half = x, high = y
__device__ __forceinline__ uint32_t pack_hi2(float x, float y) {
    uint32_t r;
    asm("prmt.b32 %0, %1, %2, 0x7632;"
        : "=r"(r) : "r"(__float_as_uint(x)), "r"(__float_as_uint(y)));
    return r;
}

// rounded bf16x2 pack: low half = lo_elem, high half = hi_elem
__device__ __forceinline__ uint32_t cvt2bf(float hi_elem, float lo_elem) {
    uint32_t r;
    asm("cvt.rn.bf16x2.f32 %0, %1, %2;" : "=r"(r) : "f"(hi_elem), "f"(lo_elem));
    return r;
}
// rounded fp16x2 pack: low half = lo_elem, high half = hi_elem
__device__ __forceinline__ uint32_t cvt2f16(float hi_elem, float lo_elem) {
    uint32_t r;
    asm("cvt.rn.f16x2.f32 %0, %1, %2;" : "=r"(r) : "f"(hi_elem), "f"(lo_elem));
    return r;
}

// fast 2^x on FMA/ALU pipes (avoids MUFU serialization)
__device__ __forceinline__ float fex2(float x) {
    x = fmaxf(x, -126.0f);
    float n = rintf(x);
    float f = x - n;
    float p = fmaf(0.0096181f, f, 0.0555036f);
    p = fmaf(p, f, 0.2402264f);
    p = fmaf(p, f, 0.6931472f);
    p = fmaf(p, f, 1.0f);
    int e = (int)n;
    return p * __int_as_float((e + 127) << 23);
}

__device__ __forceinline__ void mma_bf16(float c[4],
    uint32_t a0, uint32_t a1, uint32_t a2, uint32_t a3,
    uint32_t b0, uint32_t b1)
{
    asm volatile(
        "mma.sync.aligned.m16n8k16.row.col.f32.bf16.bf16.f32 "
        "{%0,%1,%2,%3}, {%4,%5,%6,%7}, {%8,%9}, {%0,%1,%2,%3};"
        : "+f"(c[0]), "+f"(c[1]), "+f"(c[2]), "+f"(c[3])
        : "r"(a0), "r"(a1), "r"(a2), "r"(a3), "r"(b0), "r"(b1));
}

__device__ __forceinline__ void mma_f16(float c[4],
    uint32_t a0, uint32_t a1, uint32_t a2, uint32_t a3,
    uint32_t b0, uint32_t b1)
{
    asm volatile(
        "mma.sync.aligned.m16n8k16.row.col.f32.f16.f16.f32 "
        "{%0,%1,%2,%3}, {%4,%5,%6,%7}, {%8,%9}, {%0,%1,%2,%3};"
        : "+f"(c[0]), "+f"(c[1]), "+f"(c[2]), "+f"(c[3])
        : "r"(a0), "r"(a1), "r"(a2), "r"(a3), "r"(b0), "r"(b1));
}

__device__ __forceinline__ void ldsm_x4(uint32_t r[4], uint32_t addr) {
    asm volatile("ldmatrix.sync.aligned.m8n8.x4.shared.b16 {%0,%1,%2,%3}, [%4];"
                 : "=r"(r[0]), "=r"(r[1]), "=r"(r[2]), "=r"(r[3]) : "r"(addr));
}
__device__ __forceinline__ void ldsm_x4t(uint32_t r[4], uint32_t addr) {
    asm volatile("ldmatrix.sync.aligned.m8n8.x4.trans.shared.b16 {%0,%1,%2,%3}, [%4];"
                 : "=r"(r[0]), "=r"(r[1]), "=r"(r[2]), "=r"(r[3]) : "r"(addr));
}

__device__ __forceinline__ void cpa16(uint32_t dst, const void* src) {
    asm volatile("cp.async.cg.shared.global [%0], [%1], 16;" :: "r"(dst), "l"(src));
}
#define CP_COMMIT()  asm volatile("cp.async.commit_group;" ::: "memory")
#define CP_WAIT0()   asm volatile("cp.async.wait_group 0;" ::: "memory")
#define CP_WAIT1()   asm volatile("cp.async.wait_group 1;" ::: "memory")

// copy one pre-swizzled 16KB tile (global -> smem), 256 threads
__device__ __forceinline__ void cp_tile(uint32_t dsmem, const uint8_t* g, int tid) {
#pragma unroll
    for (int i = 0; i < 4; i++)
        cpa16(dsmem + (tid + 256 * i) * 16, g + (tid + 256 * i) * 16);
}
// copy 8KB (half tile: 64 rows x 128B)
__device__ __forceinline__ void cp_half(uint32_t dsmem, const uint8_t* g, int tid) {
#pragma unroll
    for (int i = 0; i < 2; i++)
        cpa16(dsmem + (tid + 256 * i) * 16, g + (tid + 256 * i) * 16);
}

// Stage a 128x64 fp32 tile into hi/lo bf16 swizzled tiles
__device__ __forceinline__ void stage128(char* dhi, char* dlo,
    const float* __restrict__ g, int ldg, float sc, int tid)
{
#pragma unroll
    for (int i4 = tid; i4 < 2048; i4 += 256) {
        const int r = i4 >> 4, c4 = (i4 & 15) << 2;
        float4 v = *(const float4*)(g + (long long)r * ldg + c4);
        v.x *= sc; v.y *= sc; v.z *= sc; v.w *= sc;
        uint32_t h0 = pack_hi2(v.x, v.y);
        uint32_t h1 = pack_hi2(v.z, v.w);
        uint32_t l0 = cvt2bf(v.y - trunc16f(v.y), v.x - trunc16f(v.x));
        uint32_t l1 = cvt2bf(v.w - trunc16f(v.w), v.z - trunc16f(v.z));
        const uint32_t off = swz((uint32_t)(r * 128 + c4 * 2));
        *(uint2*)(dhi + off) = make_uint2(h0, h1);
        *(uint2*)(dlo + off) = make_uint2(l0, l1);
    }
}

// ===========================================================================
// Combined prep: one launch. blocks [0,256): x tiles; [256,304): W qkv;
// [304,432): Wo tiles.
// ===========================================================================
__global__ __launch_bounds__(256) void prep_all(
    const float* __restrict__ x,
    const float* __restrict__ W0, const float* __restrict__ W1,
    const float* __restrict__ W2, const float* __restrict__ Wo,
    uint8_t* __restrict__ xdst, uint8_t* __restrict__ wdst,
    uint8_t* __restrict__ wodst)
{
    const int id = blockIdx.x;
    const int tid = threadIdx.x;
    if (id < 256) {
        const int kc = id & 15, rb = id >> 4;
        uint8_t* hi = xdst + (((size_t)rb * 16 + kc) * 2 + 0) * TILE_B;
        uint8_t* lo = xdst + (((size_t)rb * 16 + kc) * 2 + 1) * TILE_B;
        stage128((char*)hi, (char*)lo, x + (long long)rb * 128 * EMB + kc * 64,
                 EMB, 1.0f, tid);
    } else if (id < 304) {
        const int i = id - 256;
        const int kc = i & 15, z = i >> 4;
        const float* W = (z == 0) ? W0 : ((z == 1) ? W1 : W2);
        uint8_t* hi = wdst + ((size_t)z * 16 + kc) * TILE_B;
        uint8_t* lo = hi + 8192;
#pragma unroll
        for (int i4 = tid; i4 < 64 * 16; i4 += 256) {
            const int r = i4 >> 4, c4 = (i4 & 15) << 2;
            float4 v = *(const float4*)(W + (long long)r * EMB + kc * 64 + c4);
            const uint32_t off = swz((uint32_t)(r * 128 + c4 * 2));
            *(uint2*)(hi + off) = make_uint2(pack_hi2(v.x, v.y), pack_hi2(v.z, v.w));
            *(uint2*)(lo + off) = make_uint2(
                cvt2bf(v.y - trunc16f(v.y), v.x - trunc16f(v.x)),
                cvt2bf(v.w - trunc16f(v.w), v.z - trunc16f(v.z)));
        }
    } else {
        const int i = id - 304;
        const int kc = i & 15, by = i >> 4;
        uint8_t* hi = wodst + (((size_t)by * 16 + kc) * 2 + 0) * TILE_B;
        uint8_t* lo = wodst + (((size_t)by * 16 + kc) * 2 + 1) * TILE_B;
        stage128((char*)hi, (char*)lo, Wo + (long long)by * 128 * EMB + kc * 64,
                 EMB, 1.0f, tid);
    }
}

// ===========================================================================
// Stage 1: K/Q/V = x @ W^T, HMMA bf16x3, K-split x2.
// grid (16 rowblk, 3 z, 2 ksplit). Each CTA: 8 kc iters -> partial fp32.
// ===========================================================================
#define QKV_SMEM 98304

__global__ __launch_bounds__(256) void gemm_qkv_hmma(
    const uint8_t* __restrict__ xbf, const uint8_t* __restrict__ wbf,
    float* __restrict__ C0, float* __restrict__ C1)
{
    extern __shared__ char sm[];
    const uint32_t base = smem_u32(sm);
    const int tid = threadIdx.x;
    const int w = tid >> 5, l = tid & 31;
    const int rl = l & 7, mi = l >> 3;
    const int rb = blockIdx.x, z = blockIdx.y, kq = blockIdx.z;
    const int kc0 = kq * 8, kc1 = kc0 + 8;

    float s[8][4];
#pragma unroll
    for (int j = 0; j < 8; j++)
#pragma unroll
        for (int k = 0; k < 4; k++) s[j][k] = 0.0f;

    auto issue = [&](int kc) {
        const uint32_t st = base + (uint32_t)(kc & 1) * 49152;
        const uint8_t* At = xbf + (((size_t)rb * 16 + kc) * 2) * TILE_B;
        const uint8_t* Bt = wbf + ((size_t)z * 16 + kc) * TILE_B;
        cp_tile(st, At, tid);
        cp_tile(st + TILE_B, At + TILE_B, tid);
        cp_tile(st + 2 * TILE_B, Bt, tid);
        CP_COMMIT();
    };

    issue(kc0);
    for (int kc = kc0; kc < kc1; kc++) {
        if (kc + 1 < kc1) { issue(kc + 1); CP_WAIT1(); } else { CP_WAIT0(); }
        __syncthreads();
        const uint32_t st = base + (uint32_t)(kc & 1) * 49152;
        const uint32_t sAH = st, sAL = st + TILE_B;
        const uint32_t sBH = st + 2 * TILE_B, sBL = st + 2 * TILE_B + 8192;

        uint32_t ah[4][4], al_[4][4];
        const int aRow = 16 * w + rl + ((mi & 1) ? 8 : 0);
        const int cAdd = (mi & 2) ? 8 : 0;
#pragma unroll
        for (int ks = 0; ks < 4; ks++) {
            const uint32_t off = swz((uint32_t)(aRow * 128 + (16 * ks + cAdd) * 2));
            ldsm_x4(ah[ks], sAH + off);
            ldsm_x4(al_[ks], sAL + off);
        }
#pragma unroll
        for (int jj = 0; jj < 4; jj++) {
            const int nrow = 16 * jj + rl + ((mi & 2) ? 8 : 0);
#pragma unroll
            for (int ks = 0; ks < 4; ks++) {
                const int kcol = 16 * ks + ((mi & 1) ? 8 : 0);
                const uint32_t off = swz((uint32_t)(nrow * 128 + kcol * 2));
                uint32_t bh[4], bl[4];
                ldsm_x4(bh, sBH + off);
                ldsm_x4(bl, sBL + off);
                mma_bf16(s[2 * jj], ah[ks][0], ah[ks][1], ah[ks][2], ah[ks][3], bh[0], bh[1]);
                mma_bf16(s[2 * jj], ah[ks][0], ah[ks][1], ah[ks][2], ah[ks][3], bl[0], bl[1]);
                mma_bf16(s[2 * jj], al_[ks][0], al_[ks][1], al_[ks][2], al_[ks][3], bh[0], bh[1]);
                mma_bf16(s[2 * jj + 1], ah[ks][0], ah[ks][1], ah[ks][2], ah[ks][3], bh[2], bh[3]);
                mma_bf16(s[2 * jj + 1], ah[ks][0], ah[ks][1], ah[ks][2], ah[ks][3], bl[2], bl[3]);
                mma_bf16(s[2 * jj + 1], al_[ks][0], al_[ks][1], al_[ks][2], al_[ks][3], bh[2], bh[3]);
            }
        }
        __syncthreads();
    }

    float* Cz = ((kq == 0) ? C0 : C1) + (size_t)z * S_LEN * DH;
    const int rit0 = rb * 128 + 16 * w + (l >> 2);
#pragma unroll
    for (int j = 0; j < 8; j++) {
        const int col = 8 * j + 2 * (l & 3);
        *(float2*)&Cz[(long long)rit0 * DH + col] = make_float2(s[j][0], s[j][1]);
        *(float2*)&Cz[(long long)(rit0 + 8) * DH + col] = make_float2(s[j][2], s[j][3]);
    }
}

// ===========================================================================
// Stage 2: per-head linears (SIMT fp32, A = partial0 + partial1) -> tiles.
// K/Q (tz 0/1): bf16 hi/lo; V (tz 2): fp16 single (hi slot). Q pre-scaled.
// ===========================================================================
__global__ __launch_bounds__(256) void gemm_heads(
    const float* __restrict__ X0, const float* __restrict__ X1,
    const float* __restrict__ Wk_, const float* __restrict__ bk_,
    const float* __restrict__ Wq_, const float* __restrict__ bq_,
    const float* __restrict__ Wv_, const float* __restrict__ bv_,
    uint8_t* __restrict__ Outbf)
{
    __shared__ float AsT[16 * 64];
    __shared__ float BsT[16 * 64];
    const int t = threadIdx.x;
    const int tx = t & 15, ty = t >> 4;
    const int bm = blockIdx.x * 64;
    const int z = blockIdx.z;
    const int tz = z >> 4, hh = z & 15;

    const size_t zofs = (size_t)tz * S_LEN * DH;
    const float* A0 = X0 + zofs;
    const float* A1 = X1 + zofs;
    const float* W = ((tz == 0) ? Wk_ : ((tz == 1) ? Wq_ : Wv_)) + hh * DH * DH;
    const float* bb = ((tz == 0) ? bk_ : ((tz == 1) ? bq_ : bv_)) + hh * DH;

    const int lm = t >> 2, k0 = (t & 3) << 2;
    float acc[4][4] = {};

    for (int kc = 0; kc < DH; kc += 16) {
        const long long aoff = (long long)(bm + lm) * DH + kc + k0;
        float4 a0v = *(const float4*)(A0 + aoff);
        float4 a1v = *(const float4*)(A1 + aoff);
        float4 av = make_float4(a0v.x + a1v.x, a0v.y + a1v.y,
                                a0v.z + a1v.z, a0v.w + a1v.w);
        float4 bv4 = *(const float4*)(W + (long long)lm * DH + kc + k0);
        __syncthreads();
        {
            float a4[4] = {av.x, av.y, av.z, av.w};
            float b4[4] = {bv4.x, bv4.y, bv4.z, bv4.w};
#pragma unroll
            for (int i = 0; i < 4; i++) {
                const int sw = (k0 + i) & 12;
                AsT[(k0 + i) * 64 + (lm ^ sw)] = a4[i];
                BsT[(k0 + i) * 64 + (lm ^ sw)] = b4[i];
            }
        }
        __syncthreads();
#pragma unroll
        for (int kk = 0; kk < 16; kk++) {
            const int sw = kk & 12;
            float4 a = *(const float4*)&AsT[kk * 64 + ((4 * ty) ^ sw)];
            float4 b = *(const float4*)&BsT[kk * 64 + ((4 * tx) ^ sw)];
            float ar[4] = {a.x, a.y, a.z, a.w};
            float br[4] = {b.x, b.y, b.z, b.w};
#pragma unroll
            for (int i = 0; i < 4; i++)
#pragma unroll
                for (int j = 0; j < 4; j++)
                    acc[i][j] = fmaf(ar[i], br[j], acc[i][j]);
        }
    }

    const float SC = (tz == 1) ? (0.125f * 1.44269504088896340736f) : 1.0f;
    float4 bias4 = *(const float4*)&bb[4 * tx];
#pragma unroll
    for (int i = 0; i < 4; i++) {
        const int row = bm + 4 * ty + i;
        const int rb = row >> 7, rit = row & 127;
        uint8_t* hi = Outbf + ((((size_t)z * 16 + rb) * 2) + 0) * TILE_B;
        uint8_t* lo = Outbf + ((((size_t)z * 16 + rb) * 2) + 1) * TILE_B;
        float v0 = (acc[i][0] + bias4.x) * SC;
        float v1 = (acc[i][1] + bias4.y) * SC;
        float v2 = (acc[i][2] + bias4.z) * SC;
        float v3 = (acc[i][3] + bias4.w) * SC;
        const uint32_t off = swz((uint32_t)(rit * 128 + 4 * tx * 2));
        if (tz == 2) {
            *(uint2*)(hi + off) = make_uint2(cvt2f16(v1, v0), cvt2f16(v3, v2));
        } else {
            *(uint2*)(hi + off) = make_uint2(pack_hi2(v0, v1), pack_hi2(v2, v3));
            *(uint2*)(lo + off) = make_uint2(
                cvt2bf(v1 - trunc16f(v1), v0 - trunc16f(v0)),
                cvt2bf(v3 - trunc16f(v3), v2 - trunc16f(v2)));
        }
    }
}

// ===========================================================================
// Stage 3: flash attention. QK^T: HMMA bf16x3; P.V: HMMA fp16x1.
// Softmax: packed bf16x2 max reduce (2 shfl), per-thread deferred row sums.
// ===========================================================================
#define ATT_SMEM 49152

__global__ __launch_bounds__(256, 2) void attn_mma(
    const uint8_t* __restrict__ Hbf, uint8_t* __restrict__ catbf)
{
    extern __shared__ char sm[];
    const uint32_t sKHI = smem_u32(sm);
    const uint32_t sKLO = sKHI + TILE_B;
    const uint32_t sVF  = sKLO + TILE_B;

    const int tid = threadIdx.x;
    const int w = tid >> 5, l = tid & 31;
    const int qb = blockIdx.x, h = blockIdx.y;
    const int rl = l & 7, mi = l >> 3;

    const uint8_t* Kt = Hbf + (((size_t)(0 * NH + h) * 16) * 2) * TILE_B;
    const uint8_t* Qt = Hbf + (((size_t)(1 * NH + h) * 16 + qb) * 2) * TILE_B;
    const uint8_t* Vt = Hbf + (((size_t)(2 * NH + h) * 16) * 2) * TILE_B;  // fp16, hi slots

    // prologue: Q into K buffers, grab fragments, then start K(0)
    cp_tile(sKHI, Qt, tid);
    cp_tile(sKLO, Qt + TILE_B, tid);
    CP_COMMIT();
    CP_WAIT0();
    __syncthreads();

    uint32_t aqh[4][4], aql[4][4];
    {
        const int aRow = 16 * w + rl + ((mi & 1) ? 8 : 0);
        const int cAdd = (mi & 2) ? 8 : 0;
#pragma unroll
        for (int s = 0; s < 4; s++) {
            const uint32_t off = swz((uint32_t)(aRow * 128 + (16 * s + cAdd) * 2));
            ldsm_x4(aqh[s], sKHI + off);
            ldsm_x4(aql[s], sKLO + off);
        }
    }
    __syncthreads();
    cp_tile(sKHI, Kt, tid);
    cp_tile(sKLO, Kt + TILE_B, tid);
    CP_COMMIT();

    float o[8][4];
#pragma unroll
    for (int j = 0; j < 8; j++)
#pragma unroll
        for (int k = 0; k < 4; k++) o[j][k] = 0.0f;
    float m0 = -1e30f, m1 = -1e30f, l0 = 0.0f, l1 = 0.0f;

    for (int kb = 0; kb < S_LEN / 128; kb++) {
        // V(kb) copy (fp16 single tile) — overlaps S phase
        cp_tile(sVF, Vt + (size_t)kb * 2 * TILE_B, tid);
        CP_COMMIT();
        CP_WAIT1();           // K(kb) complete
        __syncthreads();

#pragma unroll
        for (int hf = 0; hf < 2; hf++) {
            // ---- S = Q @ K^T (16 x 64 per warp), bf16x3
            float s[8][4];
#pragma unroll
            for (int j = 0; j < 8; j++)
#pragma unroll
                for (int k = 0; k < 4; k++) s[j][k] = 0.0f;

#pragma unroll
            for (int jj = 0; jj < 4; jj++) {
                const int nrow = hf * 64 + 16 * jj + rl + ((mi & 2) ? 8 : 0);
#pragma unroll
                for (int ks = 0; ks < 4; ks++) {
                    const int kcol = 16 * ks + ((mi & 1) ? 8 : 0);
                    const uint32_t off = swz((uint32_t)(nrow * 128 + kcol * 2));
                    uint32_t bh[4], bl[4];
                    ldsm_x4(bh, sKHI + off);
                    ldsm_x4(bl, sKLO + off);
                    mma_bf16(s[2 * jj], aqh[ks][0], aqh[ks][1], aqh[ks][2], aqh[ks][3], bh[0], bh[1]);
                    mma_bf16(s[2 * jj], aqh[ks][0], aqh[ks][1], aqh[ks][2], aqh[ks][3], bl[0], bl[1]);
                    mma_bf16(s[2 * jj], aql[ks][0], aql[ks][1], aql[ks][2], aql[ks][3], bh[0], bh[1]);
                    mma_bf16(s[2 * jj + 1], aqh[ks][0], aqh[ks][1], aqh[ks][2], aqh[ks][3], bh[2], bh[3]);
                    mma_bf16(s[2 * jj + 1], aqh[ks][0], aqh[ks][1], aqh[ks][2], aqh[ks][3], bl[2], bl[3]);
                    mma_bf16(s[2 * jj + 1], aql[ks][0], aql[ks][1], aql[ks][2], aql[ks][3], bh[2], bh[3]);
                }
            }

            // ---- online softmax: packed bf16x2 quad max-reduce (2 shfl)
            float rm0 = -1e30f, rm1 = -1e30f;
#pragma unroll
            for (int j = 0; j < 8; j++) {
                rm0 = fmaxf(rm0, fmaxf(s[j][0], s[j][1]));
                rm1 = fmaxf(rm1, fmaxf(s[j][2], s[j][3]));
            }
            {
                __nv_bfloat162 pm = __floats2bfloat162_rn(rm0, rm1);
                uint32_t pmu = reinterpret_cast<uint32_t&>(pm);
                uint32_t q1 = __shfl_xor_sync(0xffffffffu, pmu, 1);
                pm = __hmax2(pm, reinterpret_cast<__nv_bfloat162&>(q1));
                pmu = reinterpret_cast<uint32_t&>(pm);
                uint32_t q2 = __shfl_xor_sync(0xffffffffu, pmu, 2);
                pm = __hmax2(pm, reinterpret_cast<__nv_bfloat162&>(q2));
                pmu = reinterpret_cast<uint32_t&>(pm);
                rm0 = __uint_as_float(pmu << 16);
                rm1 = __uint_as_float(pmu & 0xffff0000u);
            }
            // guard band: bf16-rounded max can sit ~0.2 below true max;
            // p <= 2^0.2, still comfortably inside fp16 range.
            const float mn0 = fmaxf(m0, rm0), mn1 = fmaxf(m1, rm1);
            const float al0 = fex2(m0 - mn0), al1 = fex2(m1 - mn1);
            m0 = mn0; m1 = mn1;

            float sum0 = 0.0f, sum1 = 0.0f;
#pragma unroll
            for (int j = 0; j < 8; j++) {
                s[j][0] = fex2(s[j][0] - mn0);
                s[j][1] = fex2(s[j][1] - mn0);
                s[j][2] = fex2(s[j][2] - mn1);
                s[j][3] = fex2(s[j][3] - mn1);
                sum0 += s[j][0] + s[j][1];
                sum1 += s[j][2] + s[j][3];
            }
            // deferred reduction: keep per-thread partial sums (alpha-chain is
            // quad-uniform), quad-reduce once in the epilogue.
            l0 = l0 * al0 + sum0;
            l1 = l1 * al1 + sum1;
#pragma unroll
            for (int j = 0; j < 8; j++) {
                o[j][0] *= al0; o[j][1] *= al0;
                o[j][2] *= al1; o[j][3] *= al1;
            }

            // ---- pack P fragments (fp16)
            uint32_t paf[4][4];
#pragma unroll
            for (int ks = 0; ks < 4; ks++) {
                const int j0 = 2 * ks, j1 = 2 * ks + 1;
                paf[ks][0] = cvt2f16(s[j0][1], s[j0][0]);
                paf[ks][1] = cvt2f16(s[j0][3], s[j0][2]);
                paf[ks][2] = cvt2f16(s[j1][1], s[j1][0]);
                paf[ks][3] = cvt2f16(s[j1][3], s[j1][2]);
            }

            if (hf == 0) {
                CP_WAIT0();          // V(kb) landed
                __syncthreads();
            } else {
                __syncthreads();     // all warps done reading K
                if (kb + 1 < S_LEN / 128) {   // K(kb+1) overlaps PV(hf=1)
                    cp_tile(sKHI, Kt + (size_t)(kb + 1) * 2 * TILE_B, tid);
                    cp_tile(sKLO, Kt + (size_t)(kb + 1) * 2 * TILE_B + TILE_B, tid);
                    CP_COMMIT();
                }
            }

            // ---- O += P @ V, fp16 x1
#pragma unroll
            for (int jj = 0; jj < 4; jj++) {
                const int ncol = 16 * jj + ((mi & 2) ? 8 : 0);
#pragma unroll
                for (int ks = 0; ks < 4; ks++) {
                    const int krow = hf * 64 + 16 * ks + rl + ((mi & 1) ? 8 : 0);
                    const uint32_t off = swz((uint32_t)(krow * 128 + ncol * 2));
                    uint32_t vf[4];
                    ldsm_x4t(vf, sVF + off);
                    mma_f16(o[2 * jj], paf[ks][0], paf[ks][1], paf[ks][2], paf[ks][3], vf[0], vf[1]);
                    mma_f16(o[2 * jj + 1], paf[ks][0], paf[ks][1], paf[ks][2], paf[ks][3], vf[2], vf[3]);
                }
            }
        }
        __syncthreads();   // V buffer free for next iteration's copy
    }

    // ---- epilogue: quad-reduce row sums, normalize, write cat tiles
    l0 += __shfl_xor_sync(0xffffffffu, l0, 1);
    l0 += __shfl_xor_sync(0xffffffffu, l0, 2);
    l1 += __shfl_xor_sync(0xffffffffu, l1, 1);
    l1 += __shfl_xor_sync(0xffffffffu, l1, 2);
    const float i0 = 1.0f / l0, i1 = 1.0f / l1;
    uint8_t* chi = catbf + (((size_t)qb * NH + h) * 2 + 0) * TILE_B;
    uint8_t* clo = catbf + (((size_t)qb * NH + h) * 2 + 1) * TILE_B;
    const int rit0 = 16 * w + (l >> 2);
#pragma unroll
    for (int j = 0; j < 8; j++) {
        const int col = 8 * j + 2 * (l & 3);
        float v0 = o[j][0] * i0, v1 = o[j][1] * i0;
        float v2 = o[j][2] * i1, v3 = o[j][3] * i1;
        const uint32_t off0 = swz((uint32_t)(rit0 * 128 + col * 2));
        const uint32_t off1 = swz((uint32_t)((rit0 + 8) * 128 + col * 2));
        *(uint32_t*)(chi + off0) = pack_hi2(v0, v1);
        *(uint32_t*)(clo + off0) = cvt2bf(v1 - trunc16f(v1), v0 - trunc16f(v0));
        *(uint32_t*)(chi + off1) = pack_hi2(v2, v3);
        *(uint32_t*)(clo + off1) = cvt2bf(v3 - trunc16f(v3), v2 - trunc16f(v2));
    }
}

// ===========================================================================
// Stage 4: out = cat @ Wo^T + bo + x. bf16x3 HMMA.
// 128x64 tiles, 48KB/stage double-buffered = 96KB -> 2 CTAs/SM, grid 256.
// ===========================================================================
#define GM_SMEM 98304

__global__ __launch_bounds__(256, 2) void gemm_mma(
    const uint8_t* __restrict__ Abf, const uint8_t* __restrict__ Bbf,
    const float* __restrict__ bias, const float* __restrict__ res,
    float* __restrict__ C)
{
    extern __shared__ char sm[];
    const uint32_t base = smem_u32(sm);

    const int tid = threadIdx.x;
    const int w = tid >> 5, l = tid & 31;
    const int rl = l & 7, mi = l >> 3;
    const int wm = w & 3, wn = w >> 2;           // 4-way M (32 rows), 2-way N (32 cols)
    const int bx = blockIdx.x, by = blockIdx.y;  // (16, 16)
    const int bm = bx * 128, bn = by * 64;
    const int bhalf = (by & 1) * 8192;           // 64-row half of the stored Wo tile

    float c[2][4][4];
#pragma unroll
    for (int a = 0; a < 2; a++)
#pragma unroll
        for (int b = 0; b < 4; b++)
#pragma unroll
            for (int k = 0; k < 4; k++) c[a][b][k] = 0.0f;

    auto issue = [&](int k) {
        const uint32_t st = base + (uint32_t)(k & 1) * 49152;
        const uint8_t* At = Abf + (((size_t)bx * 16 + k) * 2) * TILE_B;
        const uint8_t* Bt = Bbf + ((((size_t)(by >> 1)) * 16 + k) * 2) * TILE_B;
        cp_tile(st,              At,          tid);
        cp_tile(st + TILE_B,     At + TILE_B, tid);
        cp_half(st + 2 * TILE_B, Bt + bhalf,  tid);
        cp_half(st + 2 * TILE_B + 8192, Bt + TILE_B + bhalf, tid);
        CP_COMMIT();
    };

    issue(0);
    for (int kc = 0; kc < 16; kc++) {
        if (kc + 1 < 16) { issue(kc + 1); CP_WAIT1(); } else { CP_WAIT0(); }
        __syncthreads();

        const uint32_t st = base + (uint32_t)(kc & 1) * 49152;
        const uint32_t sAH = st, sAL = st + TILE_B;
        const uint32_t sBH = st + 2 * TILE_B, sBL = st + 2 * TILE_B + 8192;

#pragma unroll
        for (int ks = 0; ks < 4; ks++) {
            uint32_t ah[2][4], al_[2][4];
            const int aRow0 = 32 * wm + rl + ((mi & 1) ? 8 : 0);
            const int aCAdd = (mi & 2) ? 8 : 0;
#pragma unroll
            for (int mt = 0; mt < 2; mt++) {
                const uint32_t off =
                    swz((uint32_t)((aRow0 + 16 * mt) * 128 + (16 * ks + aCAdd) * 2));
                ldsm_x4(ah[mt], sAH + off);
                ldsm_x4(al_[mt], sAL + off);
            }
            uint32_t bhf[4][2], blf[4][2];
            const int bRowAdd = (mi & 2) ? 8 : 0;
            const int bCol = 16 * ks + ((mi & 1) ? 8 : 0);
#pragma unroll
            for (int jj = 0; jj < 2; jj++) {
                const int nrow = 32 * wn + 16 * jj + rl + bRowAdd;
                const uint32_t off = swz((uint32_t)(nrow * 128 + bCol * 2));
                uint32_t t4[4], u4[4];
                ldsm_x4(t4, sBH + off);
                ldsm_x4(u4, sBL + off);
                bhf[2 * jj][0] = t4[0]; bhf[2 * jj][1] = t4[1];
                bhf[2 * jj + 1][0] = t4[2]; bhf[2 * jj + 1][1] = t4[3];
                blf[2 * jj][0] = u4[0]; blf[2 * jj][1] = u4[1];
                blf[2 * jj + 1][0] = u4[2]; blf[2 * jj + 1][1] = u4[3];
            }
#pragma unroll
            for (int mt = 0; mt < 2; mt++)
#pragma unroll
                for (int nt = 0; nt < 4; nt++) {
                    mma_bf16(c[mt][nt], ah[mt][0], ah[mt][1], ah[mt][2], ah[mt][3],
                             bhf[nt][0], bhf[nt][1]);
                    mma_bf16(c[mt][nt], ah[mt][0], ah[mt][1], ah[mt][2], ah[mt][3],
                             blf[nt][0], blf[nt][1]);
                    mma_bf16(c[mt][nt], al_[mt][0], al_[mt][1], al_[mt][2], al_[mt][3],
                             bhf[nt][0], bhf[nt][1]);
                }
        }
        __syncthreads();
    }

#pragma unroll
    for (int mt = 0; mt < 2; mt++) {
        const int row0 = bm + 32 * wm + 16 * mt + (l >> 2);
#pragma unroll
        for (int nt = 0; nt < 4; nt++) {
            const int col = bn + 32 * wn + 8 * nt + 2 * (l & 3);
            float2 bb = *(const float2*)&bias[col];
            float2 r0v = *(const float2*)&res[(long long)row0 * EMB + col];
            float2 r1v = *(const float2*)&res[(long long)(row0 + 8) * EMB + col];
            *(float2*)&C[(long long)row0 * EMB + col] =
                make_float2(c[mt][nt][0] + bb.x + r0v.x, c[mt][nt][1] + bb.y + r0v.y);
            *(float2*)&C[(long long)(row0 + 8) * EMB + col] =
                make_float2(c[mt][nt][2] + bb.x + r1v.x, c[mt][nt][3] + bb.y + r1v.y);
        }
    }
}

// ---------------------------------------------------------------------------
__global__ __launch_bounds__(256) void ln_kernel(
    const float* __restrict__ Y, const float* __restrict__ gamma,
    const float* __restrict__ beta, float* __restrict__ out)
{
    __shared__ float red1[8], red2[8];
    __shared__ float tot[2];
    const int row = blockIdx.x;
    const int t = threadIdx.x;

    float4 v = *(const float4*)(Y + (long long)row * EMB + 4 * t);
    float s1 = v.x + v.y + v.z + v.w;
    float s2 = v.x * v.x + v.y * v.y + v.z * v.z + v.w * v.w;
#pragma unroll
    for (int o_ = 16; o_ > 0; o_ >>= 1) {
        s1 += __shfl_xor_sync(0xffffffffu, s1, o_);
        s2 += __shfl_xor_sync(0xffffffffu, s2, o_);
    }
    const int wid = t >> 5, lane = t & 31;
    if (lane == 0) { red1[wid] = s1; red2[wid] = s2; }
    __syncthreads();
    if (t == 0) {
        float a = 0.0f, b = 0.0f;
#pragma unroll
        for (int i = 0; i < 8; i++) { a += red1[i]; b += red2[i]; }
        tot[0] = a; tot[1] = b;
    }
    __syncthreads();
    const float mu   = tot[0] * (1.0f / EMB);
    const float var  = tot[1] * (1.0f / EMB) - mu * mu;
    const float rstd = rsqrtf(var + 1e-5f);

    float4 g  = *(const float4*)&gamma[4 * t];
    float4 bb = *(const float4*)&beta[4 * t];
    float4 o4;
    o4.x = (v.x - mu) * rstd * g.x + bb.x;
    o4.y = (v.y - mu) * rstd * g.y + bb.y;
    o4.z = (v.z - mu) * rstd * g.z + bb.z;
    o4.w = (v.w - mu) * rstd * g.w + bb.w;
    *(float4*)&out[(long long)row * EMB + 4 * t] = o4;
}

// ---------------------------------------------------------------------------
extern "C" void kernel_launch(void* const* d_in, const int* in_sizes, int n_in,
                              void* d_out, int out_size)
{
    const float* x     = (const float*)d_in[0];
    const float* Wk    = (const float*)d_in[1];
    const float* Wq    = (const float*)d_in[2];
    const float* Wv    = (const float*)d_in[3];
    const float* hWk   = (const float*)d_in[4];
    const float* hbk   = (const float*)d_in[5];
    const float* hWv   = (const float*)d_in[6];
    const float* hbv   = (const float*)d_in[7];
    const float* hWq   = (const float*)d_in[8];
    const float* hbq   = (const float*)d_in[9];
    const float* Wo    = (const float*)d_in[10];
    const float* bo    = (const float*)d_in[11];
    const float* gamma = (const float*)d_in[12];
    const float* beta  = (const float*)d_in[13];
    float* out = (float*)d_out;

    float *pKQV, *pKQV2, *py;
    uint8_t *pxbf, *pwbf, *pHbf, *pcatbf, *pWobf;
    cudaGetSymbolAddress((void**)&pKQV,   g_KQV);
    cudaGetSymbolAddress((void**)&pKQV2,  g_KQV2);
    cudaGetSymbolAddress((void**)&py,     g_y);
    cudaGetSymbolAddress((void**)&pxbf,   g_xbf);
    cudaGetSymbolAddress((void**)&pwbf,   g_wbf);
    cudaGetSymbolAddress((void**)&pHbf,   g_Hbf);
    cudaGetSymbolAddress((void**)&pcatbf, g_catbf);
    cudaGetSymbolAddress((void**)&pWobf,  g_Wobf);

    cudaFuncSetAttribute(gemm_qkv_hmma, cudaFuncAttributeMaxDynamicSharedMemorySize, QKV_SMEM);
    cudaFuncSetAttribute(attn_mma, cudaFuncAttributeMaxDynamicSharedMemorySize, ATT_SMEM);
    cudaFuncSetAttribute(gemm_mma, cudaFuncAttributeMaxDynamicSharedMemorySize, GM_SMEM);

    // 0: all operand preps in one launch
    prep_all<<<432, 256>>>(x, Wk, Wq, Wv, Wo, pxbf, pwbf, pWobf);

    // 1: K,Q,V = x @ W^T (HMMA bf16x3, K-split x2 -> partials)
    gemm_qkv_hmma<<<dim3(16, 3, 2), 256, QKV_SMEM>>>(pxbf, pwbf, pKQV, pKQV2);

    // 2: per-head linears (A = p0+p1) -> K/Q bf16 hi/lo, V fp16 (Q pre-scaled)
    gemm_heads<<<dim3(32, 1, 48), 256>>>(pKQV, pKQV2, hWk, hbk, hWq, hbq, hWv, hbv, pHbf);

    // 3: flash attention (QK bf16x3, PV fp16) -> cat bf16 tiles
    attn_mma<<<dim3(16, NH), 256, ATT_SMEM>>>(pHbf, pcatbf);

    // 4: out = cat @ Wo^T + bo + x (HMMA bf16x3, 128x64 tiles, 2 CTA/SM)
    gemm_mma<<<dim3(16, 16), 256, GM_SMEM>>>(pcatbf, pWobf, bo, x, py);

    // 5: LayerNorm
    ln_kernel<<<S_LEN, 256>>>(py, gamma, beta, out);
}

// round 14
// speedup vs baseline: 4.0467x; 1.0412x over previous
#include <cuda_runtime.h>
#include <cuda_bf16.h>
#include <math.h>
#include <stdint.h>

#define S_LEN 2048
#define EMB   1024
#define DH    64
#define NH    16
#define TILE_B 16384   // one 128x64 bf16 tile, 128B rows, swizzled

// Scratch (device globals; no allocations allowed)
__device__ float   g_KQV[3 * S_LEN * DH];                // K,Q,V fp32 partial (K-split 0)
__device__ float   g_KQV2[3 * S_LEN * DH];               // K-split 1 partial
__device__ uint8_t g_xbf[16ull * 16 * 2 * TILE_B];       // x bf16 hi/lo tiles [rb][kc]
__device__ uint8_t g_wbf[3ull * 16 * TILE_B];            // Wk/Wq/Wv tiles [z][kc] (hi8KB+lo8KB)
__device__ uint8_t g_Hbf[3ull * NH * 16 * 2 * TILE_B];   // per-head K/Q (bf16 hi/lo), V (fp16 in hi slot)
__device__ uint8_t g_catbf[16ull * NH * 2 * TILE_B];     // attention out bf16 tiles
__device__ uint8_t g_Wobf[8ull * 16 * 2 * TILE_B];       // Wo bf16 tiles [rowblk128][kc]
__device__ float   g_y[S_LEN * EMB];                     // pre-LayerNorm

// ===========================================================================
// Helpers (baseline PTX only — build pipeline rejects sm_103a-specific ops)
// ===========================================================================
__device__ __forceinline__ uint32_t smem_u32(const void* p) {
    uint32_t a;
    asm("{ .reg .u64 t; cvta.to.shared.u64 t, %1; cvt.u32.u64 %0, t; }"
        : "=r"(a) : "l"(p));
    return a;
}

__device__ __forceinline__ uint32_t swz(uint32_t off) {
    return off ^ (((off >> 7) & 7u) << 4);
}

__device__ __forceinline__ float trunc16f(float x) {
    return __uint_as_float(__float_as_uint(x) & 0xffff0000u);
}

// pack top-16 bits (bf16 truncation) of two floats: low half = x, high = y
__device__ __forceinline__ uint32_t pack_hi2(float x, float y) {
    uint32_t r;
    asm("prmt.b32 %0, %1, %2, 0x7632;"
        : "=r"(r) : "r"(__float_as_uint(x)), "r"(__float_as_uint(y)));
    return r;
}

// rounded bf16x2 pack: low half = lo_elem, high half = hi_elem
__device__ __forceinline__ uint32_t cvt2bf(float hi_elem, float lo_elem) {
    uint32_t r;
    asm("cvt.rn.bf16x2.f32 %0, %1, %2;" : "=r"(r) : "f"(hi_elem), "f"(lo_elem));
    return r;
}
// rounded fp16x2 pack: low half = lo_elem, high half = hi_elem
__device__ __forceinline__ uint32_t cvt2f16(float hi_elem, float lo_elem) {
    uint32_t r;
    asm("cvt.rn.f16x2.f32 %0, %1, %2;" : "=r"(r) : "f"(hi_elem), "f"(lo_elem));
    return r;
}

// fast 2^x on FMA/ALU pipes (avoids MUFU serialization)
__device__ __forceinline__ float fex2(float x) {
    x = fmaxf(x, -126.0f);
    float n = rintf(x);
    float f = x - n;
    float p = fmaf(0.0096181f, f, 0.0555036f);
    p = fmaf(p, f, 0.2402264f);
    p = fmaf(p, f, 0.6931472f);
    p = fmaf(p, f, 1.0f);
    int e = (int)n;
    return p * __int_as_float((e + 127) << 23);
}

__device__ __forceinline__ void mma_bf16(float c[4],
    uint32_t a0, uint32_t a1, uint32_t a2, uint32_t a3,
    uint32_t b0, uint32_t b1)
{
    asm volatile(
        "mma.sync.aligned.m16n8k16.row.col.f32.bf16.bf16.f32 "
        "{%0,%1,%2,%3}, {%4,%5,%6,%7}, {%8,%9}, {%0,%1,%2,%3};"
        : "+f"(c[0]), "+f"(c[1]), "+f"(c[2]), "+f"(c[3])
        : "r"(a0), "r"(a1), "r"(a2), "r"(a3), "r"(b0), "r"(b1));
}

__device__ __forceinline__ void mma_f16(float c[4],
    uint32_t a0, uint32_t a1, uint32_t a2, uint32_t a3,
    uint32_t b0, uint32_t b1)
{
    asm volatile(
        "mma.sync.aligned.m16n8k16.row.col.f32.f16.f16.f32 "
        "{%0,%1,%2,%3}, {%4,%5,%6,%7}, {%8,%9}, {%0,%1,%2,%3};"
        : "+f"(c[0]), "+f"(c[1]), "+f"(c[2]), "+f"(c[3])
        : "r"(a0), "r"(a1), "r"(a2), "r"(a3), "r"(b0), "r"(b1));
}

__device__ __forceinline__ void ldsm_x4(uint32_t r[4], uint32_t addr) {
    asm volatile("ldmatrix.sync.aligned.m8n8.x4.shared.b16 {%0,%1,%2,%3}, [%4];"
                 : "=r"(r[0]), "=r"(r[1]), "=r"(r[2]), "=r"(r[3]) : "r"(addr));
}
__device__ __forceinline__ void ldsm_x4t(uint32_t r[4], uint32_t addr) {
    asm volatile("ldmatrix.sync.aligned.m8n8.x4.trans.shared.b16 {%0,%1,%2,%3}, [%4];"
                 : "=r"(r[0]), "=r"(r[1]), "=r"(r[2]), "=r"(r[3]) : "r"(addr));
}

__device__ __forceinline__ void cpa16(uint32_t dst, const void* src) {
    asm volatile("cp.async.cg.shared.global [%0], [%1], 16;" :: "r"(dst), "l"(src));
}
#define CP_COMMIT()  asm volatile("cp.async.commit_group;" ::: "memory")
#define CP_WAIT0()   asm volatile("cp.async.wait_group 0;" ::: "memory")
#define CP_WAIT1()   asm volatile("cp.async.wait_group 1;" ::: "memory")

// copy one pre-swizzled 16KB tile (global -> smem), 256 threads
__device__ __forceinline__ void cp_tile(uint32_t dsmem, const uint8_t* g, int tid) {
#pragma unroll
    for (int i = 0; i < 4; i++)
        cpa16(dsmem + (tid + 256 * i) * 16, g + (tid + 256 * i) * 16);
}
// copy 8KB (half tile: 64 rows x 128B)
__device__ __forceinline__ void cp_half(uint32_t dsmem, const uint8_t* g, int tid) {
#pragma unroll
    for (int i = 0; i < 2; i++)
        cpa16(dsmem + (tid + 256 * i) * 16, g + (tid + 256 * i) * 16);
}

// Stage a 128x64 fp32 tile into hi/lo bf16 swizzled tiles
__device__ __forceinline__ void stage128(char* dhi, char* dlo,
    const float* __restrict__ g, int ldg, float sc, int tid)
{
#pragma unroll
    for (int i4 = tid; i4 < 2048; i4 += 256) {
        const int r = i4 >> 4, c4 = (i4 & 15) << 2;
        float4 v = *(const float4*)(g + (long long)r * ldg + c4);
        v.x *= sc; v.y *= sc; v.z *= sc; v.w *= sc;
        uint32_t h0 = pack_hi2(v.x, v.y);
        uint32_t h1 = pack_hi2(v.z, v.w);
        uint32_t l0 = cvt2bf(v.y - trunc16f(v.y), v.x - trunc16f(v.x));
        uint32_t l1 = cvt2bf(v.w - trunc16f(v.w), v.z - trunc16f(v.z));
        const uint32_t off = swz((uint32_t)(r * 128 + c4 * 2));
        *(uint2*)(dhi + off) = make_uint2(h0, h1);
        *(uint2*)(dlo + off) = make_uint2(l0, l1);
    }
}

// ===========================================================================
// Combined prep: one launch. blocks [0,256): x tiles; [256,304): W qkv;
// [304,432): Wo tiles.
// ===========================================================================
__global__ __launch_bounds__(256) void prep_all(
    const float* __restrict__ x,
    const float* __restrict__ W0, const float* __restrict__ W1,
    const float* __restrict__ W2, const float* __restrict__ Wo,
    uint8_t* __restrict__ xdst, uint8_t* __restrict__ wdst,
    uint8_t* __restrict__ wodst)
{
    const int id = blockIdx.x;
    const int tid = threadIdx.x;
    if (id < 256) {
        const int kc = id & 15, rb = id >> 4;
        uint8_t* hi = xdst + (((size_t)rb * 16 + kc) * 2 + 0) * TILE_B;
        uint8_t* lo = xdst + (((size_t)rb * 16 + kc) * 2 + 1) * TILE_B;
        stage128((char*)hi, (char*)lo, x + (long long)rb * 128 * EMB + kc * 64,
                 EMB, 1.0f, tid);
    } else if (id < 304) {
        const int i = id - 256;
        const int kc = i & 15, z = i >> 4;
        const float* W = (z == 0) ? W0 : ((z == 1) ? W1 : W2);
        uint8_t* hi = wdst + ((size_t)z * 16 + kc) * TILE_B;
        uint8_t* lo = hi + 8192;
#pragma unroll
        for (int i4 = tid; i4 < 64 * 16; i4 += 256) {
            const int r = i4 >> 4, c4 = (i4 & 15) << 2;
            float4 v = *(const float4*)(W + (long long)r * EMB + kc * 64 + c4);
            const uint32_t off = swz((uint32_t)(r * 128 + c4 * 2));
            *(uint2*)(hi + off) = make_uint2(pack_hi2(v.x, v.y), pack_hi2(v.z, v.w));
            *(uint2*)(lo + off) = make_uint2(
                cvt2bf(v.y - trunc16f(v.y), v.x - trunc16f(v.x)),
                cvt2bf(v.w - trunc16f(v.w), v.z - trunc16f(v.z)));
        }
    } else {
        const int i = id - 304;
        const int kc = i & 15, by = i >> 4;
        uint8_t* hi = wodst + (((size_t)by * 16 + kc) * 2 + 0) * TILE_B;
        uint8_t* lo = wodst + (((size_t)by * 16 + kc) * 2 + 1) * TILE_B;
        stage128((char*)hi, (char*)lo, Wo + (long long)by * 128 * EMB + kc * 64,
                 EMB, 1.0f, tid);
    }
}

// ===========================================================================
// Stage 1: K/Q/V = x @ W^T, HMMA bf16x3, K-split x2.
// grid (16 rowblk, 3 z, 2 ksplit). Each CTA: 8 kc iters -> partial fp32.
// ===========================================================================
#define QKV_SMEM 98304

__global__ __launch_bounds__(256) void gemm_qkv_hmma(
    const uint8_t* __restrict__ xbf, const uint8_t* __restrict__ wbf,
    float* __restrict__ C0, float* __restrict__ C1)
{
    extern __shared__ char sm[];
    const uint32_t base = smem_u32(sm);
    const int tid = threadIdx.x;
    const int w = tid >> 5, l = tid & 31;
    const int rl = l & 7, mi = l >> 3;
    const int rb = blockIdx.x, z = blockIdx.y, kq = blockIdx.z;
    const int kc0 = kq * 8, kc1 = kc0 + 8;

    float s[8][4];
#pragma unroll
    for (int j = 0; j < 8; j++)
#pragma unroll
        for (int k = 0; k < 4; k++) s[j][k] = 0.0f;

    auto issue = [&](int kc) {
        const uint32_t st = base + (uint32_t)(kc & 1) * 49152;
        const uint8_t* At = xbf + (((size_t)rb * 16 + kc) * 2) * TILE_B;
        const uint8_t* Bt = wbf + ((size_t)z * 16 + kc) * TILE_B;
        cp_tile(st, At, tid);
        cp_tile(st + TILE_B, At + TILE_B, tid);
        cp_tile(st + 2 * TILE_B, Bt, tid);
        CP_COMMIT();
    };

    issue(kc0);
    for (int kc = kc0; kc < kc1; kc++) {
        if (kc + 1 < kc1) { issue(kc + 1); CP_WAIT1(); } else { CP_WAIT0(); }
        __syncthreads();
        const uint32_t st = base + (uint32_t)(kc & 1) * 49152;
        const uint32_t sAH = st, sAL = st + TILE_B;
        const uint32_t sBH = st + 2 * TILE_B, sBL = st + 2 * TILE_B + 8192;

        uint32_t ah[4][4], al_[4][4];
        const int aRow = 16 * w + rl + ((mi & 1) ? 8 : 0);
        const int cAdd = (mi & 2) ? 8 : 0;
#pragma unroll
        for (int ks = 0; ks < 4; ks++) {
            const uint32_t off = swz((uint32_t)(aRow * 128 + (16 * ks + cAdd) * 2));
            ldsm_x4(ah[ks], sAH + off);
            ldsm_x4(al_[ks], sAL + off);
        }
#pragma unroll
        for (int jj = 0; jj < 4; jj++) {
            const int nrow = 16 * jj + rl + ((mi & 2) ? 8 : 0);
#pragma unroll
            for (int ks = 0; ks < 4; ks++) {
                const int kcol = 16 * ks + ((mi & 1) ? 8 : 0);
                const uint32_t off = swz((uint32_t)(nrow * 128 + kcol * 2));
                uint32_t bh[4], bl[4];
                ldsm_x4(bh, sBH + off);
                ldsm_x4(bl, sBL + off);
                mma_bf16(s[2 * jj], ah[ks][0], ah[ks][1], ah[ks][2], ah[ks][3], bh[0], bh[1]);
                mma_bf16(s[2 * jj], ah[ks][0], ah[ks][1], ah[ks][2], ah[ks][3], bl[0], bl[1]);
                mma_bf16(s[2 * jj], al_[ks][0], al_[ks][1], al_[ks][2], al_[ks][3], bh[0], bh[1]);
                mma_bf16(s[2 * jj + 1], ah[ks][0], ah[ks][1], ah[ks][2], ah[ks][3], bh[2], bh[3]);
                mma_bf16(s[2 * jj + 1], ah[ks][0], ah[ks][1], ah[ks][2], ah[ks][3], bl[2], bl[3]);
                mma_bf16(s[2 * jj + 1], al_[ks][0], al_[ks][1], al_[ks][2], al_[ks][3], bh[2], bh[3]);
            }
        }
        __syncthreads();
    }

    float* Cz = ((kq == 0) ? C0 : C1) + (size_t)z * S_LEN * DH;
    const int rit0 = rb * 128 + 16 * w + (l >> 2);
#pragma unroll
    for (int j = 0; j < 8; j++) {
        const int col = 8 * j + 2 * (l & 3);
        *(float2*)&Cz[(long long)rit0 * DH + col] = make_float2(s[j][0], s[j][1]);
        *(float2*)&Cz[(long long)(rit0 + 8) * DH + col] = make_float2(s[j][2], s[j][3]);
    }
}

// ===========================================================================
// Stage 2: per-head linears (SIMT fp32, A = partial0 + partial1) -> tiles.
// K/Q (tz 0/1): bf16 hi/lo; V (tz 2): fp16 single (hi slot). Q pre-scaled.
// ===========================================================================
__global__ __launch_bounds__(256) void gemm_heads(
    const float* __restrict__ X0, const float* __restrict__ X1,
    const float* __restrict__ Wk_, const float* __restrict__ bk_,
    const float* __restrict__ Wq_, const float* __restrict__ bq_,
    const float* __restrict__ Wv_, const float* __restrict__ bv_,
    uint8_t* __restrict__ Outbf)
{
    __shared__ float AsT[16 * 64];
    __shared__ float BsT[16 * 64];
    const int t = threadIdx.x;
    const int tx = t & 15, ty = t >> 4;
    const int bm = blockIdx.x * 64;
    const int z = blockIdx.z;
    const int tz = z >> 4, hh = z & 15;

    const size_t zofs = (size_t)tz * S_LEN * DH;
    const float* A0 = X0 + zofs;
    const float* A1 = X1 + zofs;
    const float* W = ((tz == 0) ? Wk_ : ((tz == 1) ? Wq_ : Wv_)) + hh * DH * DH;
    const float* bb = ((tz == 0) ? bk_ : ((tz == 1) ? bq_ : bv_)) + hh * DH;

    const int lm = t >> 2, k0 = (t & 3) << 2;
    float acc[4][4] = {};

    for (int kc = 0; kc < DH; kc += 16) {
        const long long aoff = (long long)(bm + lm) * DH + kc + k0;
        float4 a0v = *(const float4*)(A0 + aoff);
        float4 a1v = *(const float4*)(A1 + aoff);
        float4 av = make_float4(a0v.x + a1v.x, a0v.y + a1v.y,
                                a0v.z + a1v.z, a0v.w + a1v.w);
        float4 bv4 = *(const float4*)(W + (long long)lm * DH + kc + k0);
        __syncthreads();
        {
            float a4[4] = {av.x, av.y, av.z, av.w};
            float b4[4] = {bv4.x, bv4.y, bv4.z, bv4.w};
#pragma unroll
            for (int i = 0; i < 4; i++) {
                const int sw = (k0 + i) & 12;
                AsT[(k0 + i) * 64 + (lm ^ sw)] = a4[i];
                BsT[(k0 + i) * 64 + (lm ^ sw)] = b4[i];
            }
        }
        __syncthreads();
#pragma unroll
        for (int kk = 0; kk < 16; kk++) {
            const int sw = kk & 12;
            float4 a = *(const float4*)&AsT[kk * 64 + ((4 * ty) ^ sw)];
            float4 b = *(const float4*)&BsT[kk * 64 + ((4 * tx) ^ sw)];
            float ar[4] = {a.x, a.y, a.z, a.w};
            float br[4] = {b.x, b.y, b.z, b.w};
#pragma unroll
            for (int i = 0; i < 4; i++)
#pragma unroll
                for (int j = 0; j < 4; j++)
                    acc[i][j] = fmaf(ar[i], br[j], acc[i][j]);
        }
    }

    const float SC = (tz == 1) ? (0.125f * 1.44269504088896340736f) : 1.0f;
    float4 bias4 = *(const float4*)&bb[4 * tx];
#pragma unroll
    for (int i = 0; i < 4; i++) {
        const int row = bm + 4 * ty + i;
        const int rb = row >> 7, rit = row & 127;
        uint8_t* hi = Outbf + ((((size_t)z * 16 + rb) * 2) + 0) * TILE_B;
        uint8_t* lo = Outbf + ((((size_t)z * 16 + rb) * 2) + 1) * TILE_B;
        float v0 = (acc[i][0] + bias4.x) * SC;
        float v1 = (acc[i][1] + bias4.y) * SC;
        float v2 = (acc[i][2] + bias4.z) * SC;
        float v3 = (acc[i][3] + bias4.w) * SC;
        const uint32_t off = swz((uint32_t)(rit * 128 + 4 * tx * 2));
        if (tz == 2) {
            *(uint2*)(hi + off) = make_uint2(cvt2f16(v1, v0), cvt2f16(v3, v2));
        } else {
            *(uint2*)(hi + off) = make_uint2(pack_hi2(v0, v1), pack_hi2(v2, v3));
            *(uint2*)(lo + off) = make_uint2(
                cvt2bf(v1 - trunc16f(v1), v0 - trunc16f(v0)),
                cvt2bf(v3 - trunc16f(v3), v2 - trunc16f(v2)));
        }
    }
}

// ===========================================================================
// Stage 3: flash attention. QK^T: HMMA bf16x3; P.V: HMMA fp16x1.
// K+V FULLY double-buffered (2 stages x 48KB = 96KB/CTA, 2 CTA/SM):
// exactly ONE __syncthreads per kb iteration -> warps drift out of phase,
// softmax of one warp overlaps HMMA of another (tensor-pipe bubbles gone).
// ===========================================================================
#define ATT_SMEM 98304
#define ATT_STAGE 49152

__global__ __launch_bounds__(256, 2) void attn_mma(
    const uint8_t* __restrict__ Hbf, uint8_t* __restrict__ catbf)
{
    extern __shared__ char sm[];
    const uint32_t base = smem_u32(sm);

    const int tid = threadIdx.x;
    const int w = tid >> 5, l = tid & 31;
    const int qb = blockIdx.x, h = blockIdx.y;
    const int rl = l & 7, mi = l >> 3;

    const uint8_t* Kt = Hbf + (((size_t)(0 * NH + h) * 16) * 2) * TILE_B;
    const uint8_t* Qt = Hbf + (((size_t)(1 * NH + h) * 16 + qb) * 2) * TILE_B;
    const uint8_t* Vt = Hbf + (((size_t)(2 * NH + h) * 16) * 2) * TILE_B;  // fp16, hi slots

    // stage layout: [KHI 16K | KLO 16K | VF 16K]
    auto issue = [&](int kb) {
        const uint32_t st = base + (uint32_t)(kb & 1) * ATT_STAGE;
        cp_tile(st,              Kt + (size_t)kb * 2 * TILE_B, tid);
        cp_tile(st + TILE_B,     Kt + (size_t)kb * 2 * TILE_B + TILE_B, tid);
        cp_tile(st + 2 * TILE_B, Vt + (size_t)kb * 2 * TILE_B, tid);
        CP_COMMIT();
    };

    // prologue: Q into stage0, grab fragments, then start K/V(0)
    cp_tile(base,          Qt, tid);
    cp_tile(base + TILE_B, Qt + TILE_B, tid);
    CP_COMMIT();
    CP_WAIT0();
    __syncthreads();

    uint32_t aqh[4][4], aql[4][4];
    {
        const int aRow = 16 * w + rl + ((mi & 1) ? 8 : 0);
        const int cAdd = (mi & 2) ? 8 : 0;
#pragma unroll
        for (int s = 0; s < 4; s++) {
            const uint32_t off = swz((uint32_t)(aRow * 128 + (16 * s + cAdd) * 2));
            ldsm_x4(aqh[s], base + off);
            ldsm_x4(aql[s], base + TILE_B + off);
        }
    }
    __syncthreads();
    issue(0);

    float o[8][4];
#pragma unroll
    for (int j = 0; j < 8; j++)
#pragma unroll
        for (int k = 0; k < 4; k++) o[j][k] = 0.0f;
    float m0 = -1e30f, m1 = -1e30f, l0 = 0.0f, l1 = 0.0f;

    for (int kb = 0; kb < S_LEN / 128; kb++) {
        CP_WAIT0();          // K/V(kb) landed (was issued one full iter ago)
        __syncthreads();     // ...and stage (kb+1)&1 is drained by all warps
        if (kb + 1 < S_LEN / 128) issue(kb + 1);   // overlaps ALL of this iter

        const uint32_t st = base + (uint32_t)(kb & 1) * ATT_STAGE;
        const uint32_t sKHI = st, sKLO = st + TILE_B, sVF = st + 2 * TILE_B;

#pragma unroll
        for (int hf = 0; hf < 2; hf++) {
            // ---- S = Q @ K^T (16 x 64 per warp), bf16x3
            float s[8][4];
#pragma unroll
            for (int j = 0; j < 8; j++)
#pragma unroll
                for (int k = 0; k < 4; k++) s[j][k] = 0.0f;

#pragma unroll
            for (int jj = 0; jj < 4; jj++) {
                const int nrow = hf * 64 + 16 * jj + rl + ((mi & 2) ? 8 : 0);
#pragma unroll
                for (int ks = 0; ks < 4; ks++) {
                    const int kcol = 16 * ks + ((mi & 1) ? 8 : 0);
                    const uint32_t off = swz((uint32_t)(nrow * 128 + kcol * 2));
                    uint32_t bh[4], bl[4];
                    ldsm_x4(bh, sKHI + off);
                    ldsm_x4(bl, sKLO + off);
                    mma_bf16(s[2 * jj], aqh[ks][0], aqh[ks][1], aqh[ks][2], aqh[ks][3], bh[0], bh[1]);
                    mma_bf16(s[2 * jj], aqh[ks][0], aqh[ks][1], aqh[ks][2], aqh[ks][3], bl[0], bl[1]);
                    mma_bf16(s[2 * jj], aql[ks][0], aql[ks][1], aql[ks][2], aql[ks][3], bh[0], bh[1]);
                    mma_bf16(s[2 * jj + 1], aqh[ks][0], aqh[ks][1], aqh[ks][2], aqh[ks][3], bh[2], bh[3]);
                    mma_bf16(s[2 * jj + 1], aqh[ks][0], aqh[ks][1], aqh[ks][2], aqh[ks][3], bl[2], bl[3]);
                    mma_bf16(s[2 * jj + 1], aql[ks][0], aql[ks][1], aql[ks][2], aql[ks][3], bh[2], bh[3]);
                }
            }

            // ---- online softmax: packed bf16x2 quad max-reduce (2 shfl)
            float rm0 = -1e30f, rm1 = -1e30f;
#pragma unroll
            for (int j = 0; j < 8; j++) {
                rm0 = fmaxf(rm0, fmaxf(s[j][0], s[j][1]));
                rm1 = fmaxf(rm1, fmaxf(s[j][2], s[j][3]));
            }
            {
                __nv_bfloat162 pm = __floats2bfloat162_rn(rm0, rm1);
                uint32_t pmu = reinterpret_cast<uint32_t&>(pm);
                uint32_t q1 = __shfl_xor_sync(0xffffffffu, pmu, 1);
                pm = __hmax2(pm, reinterpret_cast<__nv_bfloat162&>(q1));
                pmu = reinterpret_cast<uint32_t&>(pm);
                uint32_t q2 = __shfl_xor_sync(0xffffffffu, pmu, 2);
                pm = __hmax2(pm, reinterpret_cast<__nv_bfloat162&>(q2));
                pmu = reinterpret_cast<uint32_t&>(pm);
                rm0 = __uint_as_float(pmu << 16);
                rm1 = __uint_as_float(pmu & 0xffff0000u);
            }
            const float mn0 = fmaxf(m0, rm0), mn1 = fmaxf(m1, rm1);
            const float al0 = fex2(m0 - mn0), al1 = fex2(m1 - mn1);
            m0 = mn0; m1 = mn1;

            float sum0 = 0.0f, sum1 = 0.0f;
#pragma unroll
            for (int j = 0; j < 8; j++) {
                s[j][0] = fex2(s[j][0] - mn0);
                s[j][1] = fex2(s[j][1] - mn0);
                s[j][2] = fex2(s[j][2] - mn1);
                s[j][3] = fex2(s[j][3] - mn1);
                sum0 += s[j][0] + s[j][1];
                sum1 += s[j][2] + s[j][3];
            }
            l0 = l0 * al0 + sum0;
            l1 = l1 * al1 + sum1;
#pragma unroll
            for (int j = 0; j < 8; j++) {
                o[j][0] *= al0; o[j][1] *= al0;
                o[j][2] *= al1; o[j][3] *= al1;
            }

            // ---- pack P fragments (fp16)
            uint32_t paf[4][4];
#pragma unroll
            for (int ks = 0; ks < 4; ks++) {
                const int j0 = 2 * ks, j1 = 2 * ks + 1;
                paf[ks][0] = cvt2f16(s[j0][1], s[j0][0]);
                paf[ks][1] = cvt2f16(s[j0][3], s[j0][2]);
                paf[ks][2] = cvt2f16(s[j1][1], s[j1][0]);
                paf[ks][3] = cvt2f16(s[j1][3], s[j1][2]);
            }

            // ---- O += P @ V, fp16 x1 (no barriers: per-warp private work)
#pragma unroll
            for (int jj = 0; jj < 4; jj++) {
                const int ncol = 16 * jj + ((mi & 2) ? 8 : 0);
#pragma unroll
                for (int ks = 0; ks < 4; ks++) {
                    const int krow = hf * 64 + 16 * ks + rl + ((mi & 1) ? 8 : 0);
                    const uint32_t off = swz((uint32_t)(krow * 128 + ncol * 2));
                    uint32_t vf[4];
                    ldsm_x4t(vf, sVF + off);
                    mma_f16(o[2 * jj], paf[ks][0], paf[ks][1], paf[ks][2], paf[ks][3], vf[0], vf[1]);
                    mma_f16(o[2 * jj + 1], paf[ks][0], paf[ks][1], paf[ks][2], paf[ks][3], vf[2], vf[3]);
                }
            }
        }
        // no trailing barrier: next iteration's top syncthreads covers reuse
    }

    // ---- epilogue: quad-reduce row sums, normalize, write cat tiles
    l0 += __shfl_xor_sync(0xffffffffu, l0, 1);
    l0 += __shfl_xor_sync(0xffffffffu, l0, 2);
    l1 += __shfl_xor_sync(0xffffffffu, l1, 1);
    l1 += __shfl_xor_sync(0xffffffffu, l1, 2);
    const float i0 = 1.0f / l0, i1 = 1.0f / l1;
    uint8_t* chi = catbf + (((size_t)qb * NH + h) * 2 + 0) * TILE_B;
    uint8_t* clo = catbf + (((size_t)qb * NH + h) * 2 + 1) * TILE_B;
    const int rit0 = 16 * w + (l >> 2);
#pragma unroll
    for (int j = 0; j < 8; j++) {
        const int col = 8 * j + 2 * (l & 3);
        float v0 = o[j][0] * i0, v1 = o[j][1] * i0;
        float v2 = o[j][2] * i1, v3 = o[j][3] * i1;
        const uint32_t off0 = swz((uint32_t)(rit0 * 128 + col * 2));
        const uint32_t off1 = swz((uint32_t)((rit0 + 8) * 128 + col * 2));
        *(uint32_t*)(chi + off0) = pack_hi2(v0, v1);
        *(uint32_t*)(clo + off0) = cvt2bf(v1 - trunc16f(v1), v0 - trunc16f(v0));
        *(uint32_t*)(chi + off1) = pack_hi2(v2, v3);
        *(uint32_t*)(clo + off1) = cvt2bf(v3 - trunc16f(v3), v2 - trunc16f(v2));
    }
}

// ===========================================================================
// Stage 4: out = cat @ Wo^T + bo + x. bf16x3 HMMA.
// 128x64 tiles, 48KB/stage double-buffered = 96KB -> 2 CTAs/SM, grid 256.
// ===========================================================================
#define GM_SMEM 98304

__global__ __launch_bounds__(256, 2) void gemm_mma(
    const uint8_t* __restrict__ Abf, const uint8_t* __restrict__ Bbf,
    const float* __restrict__ bias, const float* __restrict__ res,
    float* __restrict__ C)
{
    extern __shared__ char sm[];
    const uint32_t base = smem_u32(sm);

    const int tid = threadIdx.x;
    const int w = tid >> 5, l = tid & 31;
    const int rl = l & 7, mi = l >> 3;
    const int wm = w & 3, wn = w >> 2;           // 4-way M (32 rows), 2-way N (32 cols)
    const int bx = blockIdx.x, by = blockIdx.y;  // (16, 16)
    const int bm = bx * 128, bn = by * 64;
    const int bhalf = (by & 1) * 8192;           // 64-row half of the stored Wo tile

    float c[2][4][4];
#pragma unroll
    for (int a = 0; a < 2; a++)
#pragma unroll
        for (int b = 0; b < 4; b++)
#pragma unroll
            for (int k = 0; k < 4; k++) c[a][b][k] = 0.0f;

    auto issue = [&](int k) {
        const uint32_t st = base + (uint32_t)(k & 1) * 49152;
        const uint8_t* At = Abf + (((size_t)bx * 16 + k) * 2) * TILE_B;
        const uint8_t* Bt = Bbf + ((((size_t)(by >> 1)) * 16 + k) * 2) * TILE_B;
        cp_tile(st,              At,          tid);
        cp_tile(st + TILE_B,     At + TILE_B, tid);
        cp_half(st + 2 * TILE_B, Bt + bhalf,  tid);
        cp_half(st + 2 * TILE_B + 8192, Bt + TILE_B + bhalf, tid);
        CP_COMMIT();
    };

    issue(0);
    for (int kc = 0; kc < 16; kc++) {
        if (kc + 1 < 16) { issue(kc + 1); CP_WAIT1(); } else { CP_WAIT0(); }
        __syncthreads();

        const uint32_t st = base + (uint32_t)(kc & 1) * 49152;
        const uint32_t sAH = st, sAL = st + TILE_B;
        const uint32_t sBH = st + 2 * TILE_B, sBL = st + 2 * TILE_B + 8192;

#pragma unroll
        for (int ks = 0; ks < 4; ks++) {
            uint32_t ah[2][4], al_[2][4];
            const int aRow0 = 32 * wm + rl + ((mi & 1) ? 8 : 0);
            const int aCAdd = (mi & 2) ? 8 : 0;
#pragma unroll
            for (int mt = 0; mt < 2; mt++) {
                const uint32_t off =
                    swz((uint32_t)((aRow0 + 16 * mt) * 128 + (16 * ks + aCAdd) * 2));
                ldsm_x4(ah[mt], sAH + off);
                ldsm_x4(al_[mt], sAL + off);
            }
            uint32_t bhf[4][2], blf[4][2];
            const int bRowAdd = (mi & 2) ? 8 : 0;
            const int bCol = 16 * ks + ((mi & 1) ? 8 : 0);
#pragma unroll
            for (int jj = 0; jj < 2; jj++) {
                const int nrow = 32 * wn + 16 * jj + rl + bRowAdd;
                const uint32_t off = swz((uint32_t)(nrow * 128 + bCol * 2));
                uint32_t t4[4], u4[4];
                ldsm_x4(t4, sBH + off);
                ldsm_x4(u4, sBL + off);
                bhf[2 * jj][0] = t4[0]; bhf[2 * jj][1] = t4[1];
                bhf[2 * jj + 1][0] = t4[2]; bhf[2 * jj + 1][1] = t4[3];
                blf[2 * jj][0] = u4[0]; blf[2 * jj][1] = u4[1];
                blf[2 * jj + 1][0] = u4[2]; blf[2 * jj + 1][1] = u4[3];
            }
#pragma unroll
            for (int mt = 0; mt < 2; mt++)
#pragma unroll
                for (int nt = 0; nt < 4; nt++) {
                    mma_bf16(c[mt][nt], ah[mt][0], ah[mt][1], ah[mt][2], ah[mt][3],
                             bhf[nt][0], bhf[nt][1]);
                    mma_bf16(c[mt][nt], ah[mt][0], ah[mt][1], ah[mt][2], ah[mt][3],
                             blf[nt][0], blf[nt][1]);
                    mma_bf16(c[mt][nt], al_[mt][0], al_[mt][1], al_[mt][2], al_[mt][3],
                             bhf[nt][0], bhf[nt][1]);
                }
        }
        __syncthreads();
    }

#pragma unroll
    for (int mt = 0; mt < 2; mt++) {
        const int row0 = bm + 32 * wm + 16 * mt + (l >> 2);
#pragma unroll
        for (int nt = 0; nt < 4; nt++) {
            const int col = bn + 32 * wn + 8 * nt + 2 * (l & 3);
            float2 bb = *(const float2*)&bias[col];
            float2 r0v = *(const float2*)&res[(long long)row0 * EMB + col];
            float2 r1v = *(const float2*)&res[(long long)(row0 + 8) * EMB + col];
            *(float2*)&C[(long long)row0 * EMB + col] =
                make_float2(c[mt][nt][0] + bb.x + r0v.x, c[mt][nt][1] + bb.y + r0v.y);
            *(float2*)&C[(long long)(row0 + 8) * EMB + col] =
                make_float2(c[mt][nt][2] + bb.x + r1v.x, c[mt][nt][3] + bb.y + r1v.y);
        }
    }
}

// ---------------------------------------------------------------------------
__global__ __launch_bounds__(256) void ln_kernel(
    const float* __restrict__ Y, const float* __restrict__ gamma,
    const float* __restrict__ beta, float* __restrict__ out)
{
    __shared__ float red1[8], red2[8];
    __shared__ float tot[2];
    const int row = blockIdx.x;
    const int t = threadIdx.x;

    float4 v = *(const float4*)(Y + (long long)row * EMB + 4 * t);
    float s1 = v.x + v.y + v.z + v.w;
    float s2 = v.x * v.x + v.y * v.y + v.z * v.z + v.w * v.w;
#pragma unroll
    for (int o_ = 16; o_ > 0; o_ >>= 1) {
        s1 += __shfl_xor_sync(0xffffffffu, s1, o_);
        s2 += __shfl_xor_sync(0xffffffffu, s2, o_);
    }
    const int wid = t >> 5, lane = t & 31;
    if (lane == 0) { red1[wid] = s1; red2[wid] = s2; }
    __syncthreads();
    if (t == 0) {
        float a = 0.0f, b = 0.0f;
#pragma unroll
        for (int i = 0; i < 8; i++) { a += red1[i]; b += red2[i]; }
        tot[0] = a; tot[1] = b;
    }
    __syncthreads();
    const float mu   = tot[0] * (1.0f / EMB);
    const float var  = tot[1] * (1.0f / EMB) - mu * mu;
    const float rstd = rsqrtf(var + 1e-5f);

    float4 g  = *(const float4*)&gamma[4 * t];
    float4 bb = *(const float4*)&beta[4 * t];
    float4 o4;
    o4.x = (v.x - mu) * rstd * g.x + bb.x;
    o4.y = (v.y - mu) * rstd * g.y + bb.y;
    o4.z = (v.z - mu) * rstd * g.z + bb.z;
    o4.w = (v.w - mu) * rstd * g.w + bb.w;
    *(float4*)&out[(long long)row * EMB + 4 * t] = o4;
}

// ---------------------------------------------------------------------------
extern "C" void kernel_launch(void* const* d_in, const int* in_sizes, int n_in,
                              void* d_out, int out_size)
{
    const float* x     = (const float*)d_in[0];
    const float* Wk    = (const float*)d_in[1];
    const float* Wq    = (const float*)d_in[2];
    const float* Wv    = (const float*)d_in[3];
    const float* hWk   = (const float*)d_in[4];
    const float* hbk   = (const float*)d_in[5];
    const float* hWv   = (const float*)d_in[6];
    const float* hbv   = (const float*)d_in[7];
    const float* hWq   = (const float*)d_in[8];
    const float* hbq   = (const float*)d_in[9];
    const float* Wo    = (const float*)d_in[10];
    const float* bo    = (const float*)d_in[11];
    const float* gamma = (const float*)d_in[12];
    const float* beta  = (const float*)d_in[13];
    float* out = (float*)d_out;

    float *pKQV, *pKQV2, *py;
    uint8_t *pxbf, *pwbf, *pHbf, *pcatbf, *pWobf;
    cudaGetSymbolAddress((void**)&pKQV,   g_KQV);
    cudaGetSymbolAddress((void**)&pKQV2,  g_KQV2);
    cudaGetSymbolAddress((void**)&py,     g_y);
    cudaGetSymbolAddress((void**)&pxbf,   g_xbf);
    cudaGetSymbolAddress((void**)&pwbf,   g_wbf);
    cudaGetSymbolAddress((void**)&pHbf,   g_Hbf);
    cudaGetSymbolAddress((void**)&pcatbf, g_catbf);
    cudaGetSymbolAddress((void**)&pWobf,  g_Wobf);

    cudaFuncSetAttribute(gemm_qkv_hmma, cudaFuncAttributeMaxDynamicSharedMemorySize, QKV_SMEM);
    cudaFuncSetAttribute(attn_mma, cudaFuncAttributeMaxDynamicSharedMemorySize, ATT_SMEM);
    cudaFuncSetAttribute(gemm_mma, cudaFuncAttributeMaxDynamicSharedMemorySize, GM_SMEM);

    // 0: all operand preps in one launch
    prep_all<<<432, 256>>>(x, Wk, Wq, Wv, Wo, pxbf, pwbf, pWobf);

    // 1: K,Q,V = x @ W^T (HMMA bf16x3, K-split x2 -> partials)
    gemm_qkv_hmma<<<dim3(16, 3, 2), 256, QKV_SMEM>>>(pxbf, pwbf, pKQV, pKQV2);

    // 2: per-head linears (A = p0+p1) -> K/Q bf16 hi/lo, V fp16 (Q pre-scaled)
    gemm_heads<<<dim3(32, 1, 48), 256>>>(pKQV, pKQV2, hWk, hbk, hWq, hbq, hWv, hbv, pHbf);

    // 3: flash attention (QK bf16x3, PV fp16; 1 barrier/iter, K+V double-buffered)
    attn_mma<<<dim3(16, NH), 256, ATT_SMEM>>>(pHbf, pcatbf);

    // 4: out = cat @ Wo^T + bo + x (HMMA bf16x3, 128x64 tiles, 2 CTA/SM)
    gemm_mma<<<dim3(16, 16), 256, GM_SMEM>>>(pcatbf, pWobf, bo, x, py);

    // 5: LayerNorm
    ln_kernel<<<S_LEN, 256>>>(py, gamma, beta, out);
}